// round 6
// baseline (speedup 1.0000x reference)
#include <cuda_runtime.h>
#include <math.h>

#define EPSJ 1e-6f
#define NB   2000
#define DIM  4000
#define DIMP 4096
#define NE   6000
#define LDA  4128
#define NTHREADS 512
#define NWARPS   (NTHREADS / 32)
#define NBLK 128              /* LU panel width */
#define PW   128              /* substitution panel width */

__device__ float d_J[(size_t)DIMP * LDA];
__device__ float d_x[DIMP];
__device__ float d_y[DIMP];
__device__ float d_Pacc[NB];
__device__ float d_Qacc[NB];
__device__ float d_kp[NB];
__device__ float d_kq[NB];
__device__ volatile unsigned d_bar_gen;
__device__ unsigned d_bar_cnt;

struct Params {
    const float* x_in; const int* ei;
    const float *br_r, *br_x, *g_fr, *b_fr, *g_to, *b_to, *tap, *shift;
    const float *p_spec, *q_spec, *gs, *bs;
    const int* bt; const float* vmset;
    float* out;
};

struct SM {
    union {
        float diag[128][129];
        struct { float su[128][129]; float sa[64][129]; float sinv[128]; } tr;
        struct { float sl[128][129]; float sa[128][65]; } tc;
        struct { float As[2][16][132]; float Bs[2][16][132]; } gemm;
        struct { float m[128][129]; float y[128]; float inv[128]; float yc[128]; } sub;
    };
};
#define SMEM_BYTES sizeof(SM)

/* ---------- f32x2 packed-FMA helpers ---------- */
__device__ __forceinline__ unsigned long long pk2(float x)
{
    unsigned long long r;
    asm("mov.b64 %0, {%1, %1};" : "=l"(r) : "f"(x));
    return r;
}
__device__ __forceinline__ void fma2(unsigned long long& d,
                                     unsigned long long a, unsigned long long b)
{
    asm("fma.rn.f32x2 %0, %1, %2, %0;" : "+l"(d) : "l"(a), "l"(b));
}
__device__ __forceinline__ float2 upk(unsigned long long v)
{
    float lo, hi;
    asm("mov.b64 {%0, %1}, %2;" : "=f"(lo), "=f"(hi) : "l"(v));
    return make_float2(lo, hi);
}

/* ---------- software grid barrier (simple, proven) ---------- */
__device__ __forceinline__ void gsync()
{
    __syncthreads();
    if (threadIdx.x == 0) {
        __threadfence();
        unsigned gen = d_bar_gen;
        if (atomicAdd(&d_bar_cnt, 1u) == gridDim.x - 1) {
            d_bar_cnt = 0;
            __threadfence();
            d_bar_gen = gen + 1;
        } else {
            while (d_bar_gen == gen) { }
            __threadfence();
        }
    }
    __syncthreads();
}

/* ---------- LU 128x128 diagonal factor (no pivot), one block ---------- */
__device__ void lu_diag(int k, SM* sm)
{
    float (*s)[129] = sm->diag;
    const int tid = threadIdx.x;
    __syncthreads();
    for (int idx = tid; idx < 128 * 128; idx += NTHREADS)
        s[idx >> 7][idx & 127] = d_J[(size_t)(k + (idx >> 7)) * LDA + k + (idx & 127)];
    __syncthreads();
    const int i = tid & 127, grp = tid >> 7;   /* 4 col-groups */
    for (int j = 0; j < 127; j++) {
        float lij = (i > j) ? s[i][j] * (1.f / s[j][j]) : 0.f;
        if (i > j)
            for (int c = grp; c < 128; c += 4)
                if (c > j) s[i][c] -= lij * s[j][c];
        __syncthreads();
    }
    for (int idx = tid; idx < 128 * 128; idx += NTHREADS) {
        int r = idx >> 7, c = idx & 127;
        float v = s[r][c];
        if (r > c) v *= (1.f / s[c][c]);
        d_J[(size_t)(k + r) * LDA + k + c] = v;
    }
}

/* ---------- L21 tile (64 rows) = A21 * U11^{-1}, U11 128x128 ---------- */
__device__ void trsm_row(int k, int r0, SM* sm)
{
    float (*su)[129] = sm->tr.su;
    float (*sa)[129] = sm->tr.sa;
    float* sinv = sm->tr.sinv;
    const int tid = threadIdx.x;
    __syncthreads();
    for (int idx = tid; idx < 128 * 128; idx += NTHREADS)
        su[idx >> 7][idx & 127] = d_J[(size_t)(k + (idx >> 7)) * LDA + k + (idx & 127)];
    for (int idx = tid; idx < 64 * 128; idx += NTHREADS)
        sa[idx >> 7][idx & 127] = d_J[(size_t)(r0 + (idx >> 7)) * LDA + k + (idx & 127)];
    __syncthreads();
    if (tid < 128) sinv[tid] = 1.f / su[tid][tid];
    __syncthreads();
    for (int idx = tid; idx < 128 * 128; idx += NTHREADS)
        su[idx >> 7][idx & 127] *= sinv[idx >> 7];
    __syncthreads();
    const int i = tid & 63, grp = tid >> 6;    /* 8 col-groups */
    for (int j = 0; j < 127; j++) {
        float aij = sa[i][j];
        for (int c = grp; c < 128; c += 8)
            if (c > j) sa[i][c] -= aij * su[j][c];
        __syncthreads();
    }
    for (int idx = tid; idx < 64 * 128; idx += NTHREADS) {
        int r = idx >> 7, j = idx & 127;
        d_J[(size_t)(r0 + r) * LDA + k + j] = sa[r][j] * sinv[j];
    }
}

/* ---------- U12 tile (64 cols) = L11^{-1} * A12, L11 128x128 unit ---------- */
__device__ void trsm_col(int k, int c0, SM* sm)
{
    float (*sl)[129] = sm->tc.sl;
    float (*sa)[65]  = sm->tc.sa;
    const int tid = threadIdx.x;
    __syncthreads();
    for (int idx = tid; idx < 128 * 128; idx += NTHREADS)
        sl[idx >> 7][idx & 127] = d_J[(size_t)(k + (idx >> 7)) * LDA + k + (idx & 127)];
    for (int idx = tid; idx < 128 * 64; idx += NTHREADS)
        sa[idx >> 6][idx & 63] = d_J[(size_t)(k + (idx >> 6)) * LDA + c0 + (idx & 63)];
    __syncthreads();
    const int c = tid & 63, rg = tid >> 6;     /* 8 row-groups */
    for (int j = 0; j < 127; j++) {
        float ajc = sa[j][c];
        for (int i2 = rg; i2 < 128; i2 += 8)
            if (i2 > j) sa[i2][c] -= sl[i2][j] * ajc;
        __syncthreads();
    }
    for (int idx = tid; idx < 128 * 64; idx += NTHREADS)
        d_J[(size_t)(k + (idx >> 6)) * LDA + c0 + (idx & 63)] = sa[idx >> 6][idx & 63];
}

/* ---------- trailing update tile: 128x128, K=128, f32x2, double-buffered ---------- */
__device__ void gemm_tile(int k, int m, int row0, int col0, SM* sm)
{
    const int k2 = k + NBLK;
    const int tid = threadIdx.x;
    const int ty = tid >> 5;
    const int tx = tid & 31;
    const int ai = tid >> 2;
    const int aj = (tid & 3) << 2;
    const int bk = tid >> 5;
    const int bc = (tid & 31) << 2;
    const bool arow_ok = (row0 + ai) < m;
    const bool bcol_ok = (col0 + bc) < m;
    const float* gA = &d_J[(size_t)(k2 + row0 + ai) * LDA + k + aj];
    const float* gB = &d_J[(size_t)(k + bk) * LDA + k2 + col0 + bc];

    unsigned long long acc[4][4];
#pragma unroll
    for (int u = 0; u < 4; u++)
#pragma unroll
        for (int v = 0; v < 4; v++) acc[u][v] = 0ull;

    float4 z4 = make_float4(0.f, 0.f, 0.f, 0.f);
    float4 ra = arow_ok ? *(const float4*)gA : z4;
    float4 rb = bcol_ok ? *(const float4*)gB : z4;

    __syncthreads();
    sm->gemm.As[0][aj + 0][ai] = ra.x;
    sm->gemm.As[0][aj + 1][ai] = ra.y;
    sm->gemm.As[0][aj + 2][ai] = ra.z;
    sm->gemm.As[0][aj + 3][ai] = ra.w;
    *(float4*)&sm->gemm.Bs[0][bk][bc] = rb;
    __syncthreads();

    for (int c = 0; c < 8; c++) {              /* 8 chunks of K=16 */
        const int cur = c & 1;
        float4 na, nb;
        if (c < 7) {
            na = arow_ok ? *(const float4*)(gA + (c + 1) * 16) : z4;
            nb = bcol_ok ? *(const float4*)(gB + (size_t)(c + 1) * 16 * LDA) : z4;
        }
#pragma unroll
        for (int kk = 0; kk < 16; kk++) {
            const unsigned long long* ap =
                (const unsigned long long*)&sm->gemm.As[cur][kk][ty * 8];
            unsigned long long a0 = ap[0], a1 = ap[1], a2 = ap[2], a3 = ap[3];
            float4 bv = *(const float4*)&sm->gemm.Bs[cur][kk][tx * 4];
            unsigned long long b0 = pk2(bv.x), b1 = pk2(bv.y),
                               b2 = pk2(bv.z), b3 = pk2(bv.w);
            fma2(acc[0][0], a0, b0); fma2(acc[0][1], a0, b1);
            fma2(acc[0][2], a0, b2); fma2(acc[0][3], a0, b3);
            fma2(acc[1][0], a1, b0); fma2(acc[1][1], a1, b1);
            fma2(acc[1][2], a1, b2); fma2(acc[1][3], a1, b3);
            fma2(acc[2][0], a2, b0); fma2(acc[2][1], a2, b1);
            fma2(acc[2][2], a2, b2); fma2(acc[2][3], a2, b3);
            fma2(acc[3][0], a3, b0); fma2(acc[3][1], a3, b1);
            fma2(acc[3][2], a3, b2); fma2(acc[3][3], a3, b3);
        }
        if (c < 7) {
            const int nxt = cur ^ 1;
            sm->gemm.As[nxt][aj + 0][ai] = na.x;
            sm->gemm.As[nxt][aj + 1][ai] = na.y;
            sm->gemm.As[nxt][aj + 2][ai] = na.z;
            sm->gemm.As[nxt][aj + 3][ai] = na.w;
            *(float4*)&sm->gemm.Bs[nxt][bk][bc] = nb;
        }
        __syncthreads();
    }

#pragma unroll
    for (int u = 0; u < 4; u++) {
        int r0 = row0 + ty * 8 + u * 2;
        if (r0 < m && (col0 + tx * 4) < m) {
            float2 p0 = upk(acc[u][0]), p1 = upk(acc[u][1]);
            float2 p2 = upk(acc[u][2]), p3 = upk(acc[u][3]);
            float4* c0 = (float4*)&d_J[(size_t)(k2 + r0) * LDA + k2 + col0 + tx * 4];
            float4 v0 = *c0;
            v0.x -= p0.x; v0.y -= p1.x; v0.z -= p2.x; v0.w -= p3.x;
            *c0 = v0;
            float4* c1 = (float4*)&d_J[(size_t)(k2 + r0 + 1) * LDA + k2 + col0 + tx * 4];
            float4 v1 = *c1;
            v1.x -= p0.y; v1.y -= p1.y; v1.z -= p2.y; v1.w -= p3.y;
            *c1 = v1;
        }
    }
}

/* ---------- 128-wide substitution diagonal solves ---------- */
__device__ void subst_diag_fwd128(int k, SM* sm)
{
    int t = threadIdx.x;
    __syncthreads();
    for (int idx = t; idx < 128 * 128; idx += NTHREADS)
        sm->sub.m[idx >> 7][idx & 127] = d_J[(size_t)(k + (idx >> 7)) * LDA + k + (idx & 127)];
    if (t < 128) sm->sub.y[t] = d_y[k + t];
    __syncthreads();
    for (int j = 0; j < 127; j++) {
        if (t > j && t < 128) sm->sub.y[t] -= sm->sub.m[t][j] * sm->sub.y[j];
        __syncthreads();
    }
    if (t < 128) d_y[k + t] = sm->sub.y[t];
    __syncthreads();
}

__device__ void subst_diag_bwd128(int k, SM* sm)
{
    int t = threadIdx.x;
    __syncthreads();
    for (int idx = t; idx < 128 * 128; idx += NTHREADS)
        sm->sub.m[idx >> 7][idx & 127] = d_J[(size_t)(k + (idx >> 7)) * LDA + k + (idx & 127)];
    if (t < 128) sm->sub.y[t] = d_y[k + t];
    __syncthreads();
    if (t < 128) sm->sub.inv[t] = 1.f / sm->sub.m[t][t];
    __syncthreads();
    for (int j = 127; j >= 0; j--) {
        float val = sm->sub.y[j] * sm->sub.inv[j];
        if (t == j) sm->sub.y[j] = val;
        else if (t < j) sm->sub.y[t] -= sm->sub.m[t][j] * val;
        __syncthreads();
    }
    if (t < 128) d_y[k + t] = sm->sub.y[t];
    __syncthreads();
}

/* ---------- one 128-wide dot for substitution row update ---------- */
__device__ __forceinline__ void row_update(int r, int k, const float* yc, int lane)
{
    const float* row = &d_J[(size_t)r * LDA + k];
    float s = row[lane] * yc[lane] + row[lane + 32] * yc[lane + 32]
            + row[lane + 64] * yc[lane + 64] + row[lane + 96] * yc[lane + 96];
#pragma unroll
    for (int o = 16; o; o >>= 1) s += __shfl_down_sync(0xffffffffu, s, o);
    if (lane == 0) d_y[r] -= s;
}

/* =======================================================================
 *  The one persistent kernel
 * ======================================================================= */
__global__ void __launch_bounds__(NTHREADS, 1) solver_kernel(Params P)
{
    extern __shared__ char s_raw[];
    SM* sm = (SM*)s_raw;
    const int tid = threadIdx.x;
    const int gsize = gridDim.x * NTHREADS;
    const int gtid = blockIdx.x * NTHREADS + tid;
    const int warp = tid >> 5, lane = tid & 31;

    for (int i = gtid; i < DIMP; i += gsize) {
        d_x[i] = (i < DIM) ? P.x_in[i] : 0.0f;
        if (i < NB) {
            int b = P.bt[i];
            d_kp[i] = (b == 3) ? 0.f : 1.f;
            d_kq[i] = (b >= 2) ? 0.f : 1.f;
        }
    }
    gsync();

    for (int t5 = 0; t5 < 5; t5++) {
        /* ---- zero J + accumulators ---- */
        {
            size_t tot = (size_t)DIMP * LDA / 4;
            float4 z = make_float4(0.f, 0.f, 0.f, 0.f);
            for (size_t i = gtid; i < tot; i += gsize) ((float4*)d_J)[i] = z;
            for (int i = gtid; i < NB; i += gsize) { d_Pacc[i] = 0.f; d_Qacc[i] = 0.f; }
        }
        gsync();

        /* ---- edge assembly ---- */
        for (int e = gtid; e < NE; e += gsize) {
            int s = P.ei[e], d = P.ei[NE + e];
            float vm_s = d_x[NB + s], vm_d = d_x[NB + d];
            float r = P.br_r[e], xx = P.br_x[e];
            float den = r * r + xx * xx;
            float g = r / den, b = -xx / den;
            float tp = P.tap[e];
            float th = d_x[s] - d_x[d];
            float sf, cf;
            sincosf(th - P.shift[e], &sf, &cf);
            float ct = cf, st = -sf;
            float vi_t = vm_s / tp;
            float vij = vm_s * vm_d / tp;

            float gfr = P.g_fr[e], bfr = P.b_fr[e], gto = P.g_to[e], bto = P.b_to[e];
            float Pf = vi_t * vi_t * (g + gfr) + vij * (-g * cf - b * sf);
            float Qf = -vi_t * vi_t * (b + bfr) + vij * (-g * sf + b * cf);
            float Pt = vm_d * vm_d * (g + gto) + vij * (-g * ct - b * st);
            float Qt = -vm_d * vm_d * (b + bto) + vij * (-g * st + b * ct);
            atomicAdd(&d_Pacc[s], Pf); atomicAdd(&d_Pacc[d], Pt);
            atomicAdd(&d_Qacc[s], Qf); atomicAdd(&d_Qacc[d], Qt);

            float Af = g * cf + b * sf, Bf = g * sf - b * cf;
            float At = g * ct + b * st, Bt = g * st - b * ct;
            size_t Rs  = (size_t)s * LDA, Rd = (size_t)d * LDA;
            size_t Rqs = (size_t)(NB + s) * LDA, Rqd = (size_t)(NB + d) * LDA;

            if (d_kp[s] != 0.f) {
                atomicAdd(&d_J[Rs + s],      -vij * Bf);
                atomicAdd(&d_J[Rs + d],       vij * Bf);
                atomicAdd(&d_J[Rs + NB + s], -(2.f * vm_s / (tp * tp) * (g + gfr) - vm_d / tp * Af));
                atomicAdd(&d_J[Rs + NB + d],  (vm_s / tp) * Af);
            }
            if (d_kp[d] != 0.f) {
                atomicAdd(&d_J[Rd + d],      -vij * Bt);
                atomicAdd(&d_J[Rd + s],       vij * Bt);
                atomicAdd(&d_J[Rd + NB + d], -(2.f * vm_d * (g + gto) - vm_s / tp * At));
                atomicAdd(&d_J[Rd + NB + s],  (vm_d / tp) * At);
            }
            if (d_kq[s] != 0.f) {
                atomicAdd(&d_J[Rqs + s],      vij * Af);
                atomicAdd(&d_J[Rqs + d],     -vij * Af);
                atomicAdd(&d_J[Rqs + NB + s], (2.f * vm_s / (tp * tp) * (b + bfr) + vm_d / tp * Bf));
                atomicAdd(&d_J[Rqs + NB + d], (vm_s / tp) * Bf);
            }
            if (d_kq[d] != 0.f) {
                atomicAdd(&d_J[Rqd + d],      vij * At);
                atomicAdd(&d_J[Rqd + s],     -vij * At);
                atomicAdd(&d_J[Rqd + NB + d], (2.f * vm_d * (b + bto) + vm_s / tp * Bt));
                atomicAdd(&d_J[Rqd + NB + s], (vm_s / tp) * Bt);
            }
        }
        gsync();

        /* ---- diagonal terms + RHS ---- */
        for (int i = gtid; i < DIMP; i += gsize) {
            if (i < NB) {
                int b = P.bt[i];
                float vm = d_x[NB + i];
                d_J[(size_t)i * LDA + i]               += ((b == 3) ? 1.f : 0.f) + EPSJ;
                d_J[(size_t)i * LDA + NB + i]          += d_kp[i] * (-2.f * vm * P.gs[i]);
                d_J[(size_t)(NB + i) * LDA + (NB + i)] += d_kq[i] * (2.f * vm * P.bs[i]) + ((b >= 2) ? 1.f : 0.f) + EPSJ;
                d_y[i] = (b == 3) ? d_x[i] : (P.p_spec[i] - (d_Pacc[i] + vm * vm * P.gs[i]));
            } else if (i < DIM) {
                int ib = i - NB;
                float vm = d_x[i];
                d_y[i] = (P.bt[ib] >= 2) ? (vm - P.vmset[ib])
                                         : (P.q_spec[ib] - (d_Qacc[ib] - vm * vm * P.bs[ib]));
            } else {
                d_J[(size_t)i * LDA + i] = 1.0f;
                d_y[i] = 0.f;
            }
        }
        gsync();

        /* ---- blocked LU, 128-wide panels, block-0 diag lookahead ---- */
        if (blockIdx.x == 0) lu_diag(0, sm);
        gsync();
        for (int k = 0; k + NBLK < DIMP; k += NBLK) {
            int m = DIMP - k - NBLK;
            /* phase A: TRSM tiles (64-wide each) */
            {
                int ntr = m / 64;
                for (int job = blockIdx.x; job < 2 * ntr; job += gridDim.x) {
                    if (job < ntr) trsm_row(k, k + NBLK + job * 64, sm);
                    else           trsm_col(k, k + NBLK + (job - ntr) * 64, sm);
                }
            }
            gsync();
            /* phase B: GEMM; block0 does tile(0,0) then factors next diag */
            {
                int g = (m + 127) / 128;
                if (blockIdx.x == 0) {
                    gemm_tile(k, m, 0, 0, sm);
                    lu_diag(k + NBLK, sm);
                } else {
                    for (int job = blockIdx.x; job < g * g; job += gridDim.x - 1)
                        gemm_tile(k, m, (job / g) * 128, (job % g) * 128, sm);
                }
            }
            gsync();
        }

        /* ---- forward substitution, 128-wide panels, block-0 lookahead ---- */
        if (blockIdx.x == 0) subst_diag_fwd128(0, sm);
        gsync();
        for (int k = 0; k + PW < DIMP; k += PW) {
            __syncthreads();
            if (tid < PW) sm->sub.yc[tid] = d_y[k + tid];
            __syncthreads();
            if (blockIdx.x == 0) {
                for (int r = k + PW + warp; r < k + 2 * PW; r += NWARPS)
                    row_update(r, k, sm->sub.yc, lane);
                __syncthreads();
                subst_diag_fwd128(k + PW, sm);
            } else {
                int gw = (blockIdx.x - 1) * NWARPS + warp;
                int tot = (gridDim.x - 1) * NWARPS;
                for (int r = k + 2 * PW + gw; r < DIMP; r += tot)
                    row_update(r, k, sm->sub.yc, lane);
            }
            gsync();
        }

        /* ---- backward substitution ---- */
        if (blockIdx.x == 0) subst_diag_bwd128(DIMP - PW, sm);
        gsync();
        for (int k = DIMP - PW; k > 0; k -= PW) {
            __syncthreads();
            if (tid < PW) sm->sub.yc[tid] = d_y[k + tid];
            __syncthreads();
            if (blockIdx.x == 0) {
                for (int r = k - PW + warp; r < k; r += NWARPS)
                    row_update(r, k, sm->sub.yc, lane);
                __syncthreads();
                subst_diag_bwd128(k - PW, sm);
            } else {
                int gw = (blockIdx.x - 1) * NWARPS + warp;
                int tot = (gridDim.x - 1) * NWARPS;
                for (int r = gw; r < k - PW; r += tot)
                    row_update(r, k, sm->sub.yc, lane);
            }
            gsync();
        }

        /* ---- Newton update ---- */
        for (int i = gtid; i < DIM; i += gsize) {
            float v = d_x[i] - d_y[i];
            if (i >= NB) v = fminf(fmaxf(v, 0.5f), 1.5f);
            d_x[i] = v;
        }
        gsync();
    }

    for (int i = gtid; i < DIM; i += gsize)
        P.out[i] = d_x[i];
}

extern "C" void kernel_launch(void* const* d_in, const int* in_sizes, int n_in,
                              void* d_out, int out_size)
{
    Params P;
    P.x_in   = (const float*)d_in[0];
    P.ei     = (const int*)  d_in[1];
    P.br_r   = (const float*)d_in[2];
    P.br_x   = (const float*)d_in[3];
    P.g_fr   = (const float*)d_in[4];
    P.b_fr   = (const float*)d_in[5];
    P.g_to   = (const float*)d_in[6];
    P.b_to   = (const float*)d_in[7];
    P.tap    = (const float*)d_in[8];
    P.shift  = (const float*)d_in[9];
    P.p_spec = (const float*)d_in[10];
    P.q_spec = (const float*)d_in[11];
    P.gs     = (const float*)d_in[12];
    P.bs     = (const float*)d_in[13];
    P.bt     = (const int*)  d_in[14];
    P.vmset  = (const float*)d_in[15];
    P.out    = (float*)d_out;

    cudaFuncSetAttribute(solver_kernel,
                         cudaFuncAttributeMaxDynamicSharedMemorySize,
                         (int)SMEM_BYTES);

    int dev = 0, nsm = 0, per_sm = 0;
    cudaGetDevice(&dev);
    cudaDeviceGetAttribute(&nsm, cudaDevAttrMultiProcessorCount, dev);
    cudaOccupancyMaxActiveBlocksPerMultiprocessor(&per_sm, solver_kernel,
                                                  NTHREADS, SMEM_BYTES);
    if (per_sm < 1) per_sm = 1;
    int grid = nsm * per_sm;
    if (grid < 2) grid = 2;
    if (grid > 1024) grid = 1024;

    solver_kernel<<<grid, NTHREADS, SMEM_BYTES>>>(P);
}

// round 7
// speedup vs baseline: 1.3606x; 1.3606x over previous
#include <cuda_runtime.h>
#include <math.h>

#define EPSJ 1e-6f
#define NB   2000
#define DIM  4000
#define DIMP 4096
#define NE   6000
#define LDA  4128
#define NTHREADS 512
#define NWARPS   (NTHREADS / 32)
#define PW   128              /* substitution panel width */

__device__ float d_J[(size_t)DIMP * LDA];
__device__ float d_x[DIMP];
__device__ float d_y[DIMP];
__device__ float d_Pacc[NB];
__device__ float d_Qacc[NB];
__device__ float d_kp[NB];
__device__ float d_kq[NB];
__device__ volatile unsigned d_bar_gen;
__device__ unsigned d_bar_cnt;

struct Params {
    const float* x_in; const int* ei;
    const float *br_r, *br_x, *g_fr, *b_fr, *g_to, *b_to, *tap, *shift;
    const float *p_spec, *q_spec, *gs, *bs;
    const int* bt; const float* vmset;
    float* out;
};

struct SM {
    union {
        struct { float s[64][65]; } diag;
        struct { float su[64][65]; float sa[64][65]; float sinv[64]; } trsm;
        struct { float As[2][16][264]; float Bs[2][16][132]; } gemm;
        struct { float m[128][129]; float y[128]; float inv[128]; float yc[128]; } sub;
    };
};
#define SMEM_BYTES sizeof(SM)

/* ---------- f32x2 packed-FMA helpers ---------- */
__device__ __forceinline__ unsigned long long pk2(float x)
{
    unsigned long long r;
    asm("mov.b64 %0, {%1, %1};" : "=l"(r) : "f"(x));
    return r;
}
__device__ __forceinline__ void fma2(unsigned long long& d,
                                     unsigned long long a, unsigned long long b)
{
    asm("fma.rn.f32x2 %0, %1, %2, %0;" : "+l"(d) : "l"(a), "l"(b));
}
__device__ __forceinline__ float2 upk(unsigned long long v)
{
    float lo, hi;
    asm("mov.b64 {%0, %1}, %2;" : "=f"(lo), "=f"(hi) : "l"(v));
    return make_float2(lo, hi);
}

/* ---------- software grid barrier (simple, proven) ---------- */
__device__ __forceinline__ void gsync()
{
    __syncthreads();
    if (threadIdx.x == 0) {
        __threadfence();
        unsigned gen = d_bar_gen;
        if (atomicAdd(&d_bar_cnt, 1u) == gridDim.x - 1) {
            d_bar_cnt = 0;
            __threadfence();
            d_bar_gen = gen + 1;
        } else {
            while (d_bar_gen == gen) { }
            __threadfence();
        }
    }
    __syncthreads();
}

/* ---------- LU 64x64 diagonal factor (no pivot), one block ---------- */
__device__ void lu_diag(int k, SM* sm)
{
    float (*s)[65] = sm->diag.s;
    int tid = threadIdx.x;
    __syncthreads();
    for (int idx = tid; idx < 4096; idx += NTHREADS)
        s[idx >> 6][idx & 63] = d_J[(size_t)(k + (idx >> 6)) * LDA + k + (idx & 63)];
    __syncthreads();
    int i = tid & 63, cgp = tid >> 6;
    for (int j = 0; j < 64; j++) {
        float lij = (i > j) ? s[i][j] * (1.f / s[j][j]) : 0.f;
        if (i > j)
            for (int c = cgp; c < 64; c += NTHREADS / 64)
                if (c > j) s[i][c] -= lij * s[j][c];
        __syncthreads();
    }
    for (int idx = tid; idx < 4096; idx += NTHREADS) {
        int r = idx >> 6, c = idx & 63;
        float v = s[r][c];
        if (r > c) v *= (1.f / s[c][c]);
        d_J[(size_t)(k + r) * LDA + k + c] = v;
    }
}

/* ---------- L21 tile = A21 * U11^{-1} ---------- */
__device__ void trsm_row(int k, int r0, SM* sm)
{
    float (*su)[65] = sm->trsm.su;
    float (*sa)[65] = sm->trsm.sa;
    float* sinv = sm->trsm.sinv;
    int tid = threadIdx.x;
    __syncthreads();
    for (int idx = tid; idx < 4096; idx += NTHREADS) {
        int i = idx >> 6, j = idx & 63;
        su[i][j] = d_J[(size_t)(k + i) * LDA + k + j];
        sa[i][j] = d_J[(size_t)(r0 + i) * LDA + k + j];
    }
    __syncthreads();
    if (tid < 64) sinv[tid] = 1.f / su[tid][tid];
    __syncthreads();
    for (int idx = tid; idx < 4096; idx += NTHREADS)
        su[idx >> 6][idx & 63] *= sinv[idx >> 6];
    __syncthreads();
    int i = tid & 63, cgp = tid >> 6;
    for (int j = 0; j < 64; j++) {
        float aij = sa[i][j];
        for (int c = cgp; c < 64; c += NTHREADS / 64)
            if (c > j) sa[i][c] -= aij * su[j][c];
        __syncthreads();
    }
    for (int idx = tid; idx < 4096; idx += NTHREADS) {
        int r = idx >> 6, j = idx & 63;
        d_J[(size_t)(r0 + r) * LDA + k + j] = sa[r][j] * sinv[j];
    }
}

/* ---------- U12 tile = L11^{-1} * A12 ---------- */
__device__ void trsm_col(int k, int c0, SM* sm)
{
    float (*sl)[65] = sm->trsm.su;
    float (*sa)[65] = sm->trsm.sa;
    int tid = threadIdx.x;
    __syncthreads();
    for (int idx = tid; idx < 4096; idx += NTHREADS) {
        int i = idx >> 6, j = idx & 63;
        sl[i][j] = d_J[(size_t)(k + i) * LDA + k + j];
        sa[i][j] = d_J[(size_t)(k + i) * LDA + c0 + j];
    }
    __syncthreads();
    int c = tid & 63, rg = tid >> 6;
    for (int j = 0; j < 64; j++) {
        float ajc = sa[j][c];
        for (int i2 = rg; i2 < 64; i2 += NTHREADS / 64)
            if (i2 > j) sa[i2][c] -= sl[i2][j] * ajc;
        __syncthreads();
    }
    for (int idx = tid; idx < 4096; idx += NTHREADS)
        d_J[(size_t)(k + (idx >> 6)) * LDA + c0 + (idx & 63)] = sa[idx >> 6][idx & 63];
}

/* ---------- trailing update tile: 256x128, K=64, f32x2, fma-balanced ---------- */
__device__ void gemm_tile(int k, int m, int row0, int col0, SM* sm)
{
    const int k2 = k + 64;
    const int tid = threadIdx.x;
    const int ty = tid >> 4;          /* 0..31 : row-group of 8 rows */
    const int tx = tid & 15;          /* 0..15 : col-group of 8 cols */
    const int ar = tid >> 1;          /* 0..255 A loader row          */
    const int ac = (tid & 1) * 8;     /* 0 or 8 (two 8-col halves)    */
    const int bk = tid >> 5;          /* 0..15  B loader k-row        */
    const int bc = (tid & 31) * 4;    /* 0..124                       */
    const bool arow_ok = (row0 + ar) < m;
    const bool bcol_ok = (col0 + bc) < m;
    const float* gA = &d_J[(size_t)(k2 + row0 + ar) * LDA + k + ac];
    const float* gB = &d_J[(size_t)(k + bk) * LDA + k2 + col0 + bc];

    unsigned long long acc[4][8];
#pragma unroll
    for (int u = 0; u < 4; u++)
#pragma unroll
        for (int v = 0; v < 8; v++) acc[u][v] = 0ull;

    float4 z4 = make_float4(0.f, 0.f, 0.f, 0.f);
    float4 ra0 = arow_ok ? *(const float4*)gA : z4;
    float4 ra1 = arow_ok ? *(const float4*)(gA + 4) : z4;
    float4 rb  = bcol_ok ? *(const float4*)gB : z4;

    __syncthreads();                   /* union reuse guard */
    {
        float* asd = &sm->gemm.As[0][ac][ar];
        asd[0 * 264] = ra0.x; asd[1 * 264] = ra0.y;
        asd[2 * 264] = ra0.z; asd[3 * 264] = ra0.w;
        asd[4 * 264] = ra1.x; asd[5 * 264] = ra1.y;
        asd[6 * 264] = ra1.z; asd[7 * 264] = ra1.w;
        *(float4*)&sm->gemm.Bs[0][bk][bc] = rb;
    }
    __syncthreads();

    for (int c = 0; c < 4; c++) {
        const int cur = c & 1;
        float4 na0, na1, nb;
        if (c < 3) {
            na0 = arow_ok ? *(const float4*)(gA + (c + 1) * 16) : z4;
            na1 = arow_ok ? *(const float4*)(gA + (c + 1) * 16 + 4) : z4;
            nb  = bcol_ok ? *(const float4*)(gB + (size_t)(c + 1) * 16 * LDA) : z4;
        }
#pragma unroll
        for (int kk = 0; kk < 16; kk++) {
            const unsigned long long* ap =
                (const unsigned long long*)&sm->gemm.As[cur][kk][ty * 8];
            unsigned long long a0 = ap[0], a1 = ap[1], a2 = ap[2], a3 = ap[3];
            const float4 bv0 = *(const float4*)&sm->gemm.Bs[cur][kk][tx * 8];
            const float4 bv1 = *(const float4*)&sm->gemm.Bs[cur][kk][tx * 8 + 4];
            unsigned long long b0 = pk2(bv0.x), b1 = pk2(bv0.y),
                               b2 = pk2(bv0.z), b3 = pk2(bv0.w),
                               b4 = pk2(bv1.x), b5 = pk2(bv1.y),
                               b6 = pk2(bv1.z), b7 = pk2(bv1.w);
            fma2(acc[0][0], a0, b0); fma2(acc[0][1], a0, b1);
            fma2(acc[0][2], a0, b2); fma2(acc[0][3], a0, b3);
            fma2(acc[0][4], a0, b4); fma2(acc[0][5], a0, b5);
            fma2(acc[0][6], a0, b6); fma2(acc[0][7], a0, b7);
            fma2(acc[1][0], a1, b0); fma2(acc[1][1], a1, b1);
            fma2(acc[1][2], a1, b2); fma2(acc[1][3], a1, b3);
            fma2(acc[1][4], a1, b4); fma2(acc[1][5], a1, b5);
            fma2(acc[1][6], a1, b6); fma2(acc[1][7], a1, b7);
            fma2(acc[2][0], a2, b0); fma2(acc[2][1], a2, b1);
            fma2(acc[2][2], a2, b2); fma2(acc[2][3], a2, b3);
            fma2(acc[2][4], a2, b4); fma2(acc[2][5], a2, b5);
            fma2(acc[2][6], a2, b6); fma2(acc[2][7], a2, b7);
            fma2(acc[3][0], a3, b0); fma2(acc[3][1], a3, b1);
            fma2(acc[3][2], a3, b2); fma2(acc[3][3], a3, b3);
            fma2(acc[3][4], a3, b4); fma2(acc[3][5], a3, b5);
            fma2(acc[3][6], a3, b6); fma2(acc[3][7], a3, b7);
        }
        if (c < 3) {
            const int nxt = cur ^ 1;
            float* asd = &sm->gemm.As[nxt][ac][ar];
            asd[0 * 264] = na0.x; asd[1 * 264] = na0.y;
            asd[2 * 264] = na0.z; asd[3 * 264] = na0.w;
            asd[4 * 264] = na1.x; asd[5 * 264] = na1.y;
            asd[6 * 264] = na1.z; asd[7 * 264] = na1.w;
            *(float4*)&sm->gemm.Bs[nxt][bk][bc] = nb;
        }
        __syncthreads();
    }

#pragma unroll
    for (int u = 0; u < 4; u++) {
        int r0 = row0 + ty * 8 + u * 2;
        if (r0 < m && (col0 + tx * 8) < m) {
            float2 p0 = upk(acc[u][0]), p1 = upk(acc[u][1]);
            float2 p2 = upk(acc[u][2]), p3 = upk(acc[u][3]);
            float2 p4 = upk(acc[u][4]), p5 = upk(acc[u][5]);
            float2 p6 = upk(acc[u][6]), p7 = upk(acc[u][7]);
            float4* c0 = (float4*)&d_J[(size_t)(k2 + r0) * LDA + k2 + col0 + tx * 8];
            float4 v0 = c0[0], v1 = c0[1];
            v0.x -= p0.x; v0.y -= p1.x; v0.z -= p2.x; v0.w -= p3.x;
            v1.x -= p4.x; v1.y -= p5.x; v1.z -= p6.x; v1.w -= p7.x;
            c0[0] = v0; c0[1] = v1;
            float4* c1 = (float4*)&d_J[(size_t)(k2 + r0 + 1) * LDA + k2 + col0 + tx * 8];
            float4 w0 = c1[0], w1 = c1[1];
            w0.x -= p0.y; w0.y -= p1.y; w0.z -= p2.y; w0.w -= p3.y;
            w1.x -= p4.y; w1.y -= p5.y; w1.z -= p6.y; w1.w -= p7.y;
            c1[0] = w0; c1[1] = w1;
        }
    }
}

/* ---------- 128-wide substitution diagonal solves ---------- */
__device__ void subst_diag_fwd128(int k, SM* sm)
{
    int t = threadIdx.x;
    __syncthreads();
    for (int idx = t; idx < 128 * 128; idx += NTHREADS)
        sm->sub.m[idx >> 7][idx & 127] = d_J[(size_t)(k + (idx >> 7)) * LDA + k + (idx & 127)];
    if (t < 128) sm->sub.y[t] = d_y[k + t];
    __syncthreads();
    for (int j = 0; j < 127; j++) {
        if (t > j && t < 128) sm->sub.y[t] -= sm->sub.m[t][j] * sm->sub.y[j];
        __syncthreads();
    }
    if (t < 128) d_y[k + t] = sm->sub.y[t];
    __syncthreads();
}

__device__ void subst_diag_bwd128(int k, SM* sm)
{
    int t = threadIdx.x;
    __syncthreads();
    for (int idx = t; idx < 128 * 128; idx += NTHREADS)
        sm->sub.m[idx >> 7][idx & 127] = d_J[(size_t)(k + (idx >> 7)) * LDA + k + (idx & 127)];
    if (t < 128) sm->sub.y[t] = d_y[k + t];
    __syncthreads();
    if (t < 128) sm->sub.inv[t] = 1.f / sm->sub.m[t][t];
    __syncthreads();
    for (int j = 127; j >= 0; j--) {
        float val = sm->sub.y[j] * sm->sub.inv[j];
        if (t == j) sm->sub.y[j] = val;
        else if (t < j) sm->sub.y[t] -= sm->sub.m[t][j] * val;
        __syncthreads();
    }
    if (t < 128) d_y[k + t] = sm->sub.y[t];
    __syncthreads();
}

/* ---------- one 128-wide dot for substitution row update ---------- */
__device__ __forceinline__ void row_update(int r, int k, const float* yc, int lane)
{
    const float* row = &d_J[(size_t)r * LDA + k];
    float s = row[lane] * yc[lane] + row[lane + 32] * yc[lane + 32]
            + row[lane + 64] * yc[lane + 64] + row[lane + 96] * yc[lane + 96];
#pragma unroll
    for (int o = 16; o; o >>= 1) s += __shfl_down_sync(0xffffffffu, s, o);
    if (lane == 0) d_y[r] -= s;
}

/* =======================================================================
 *  The one persistent kernel
 * ======================================================================= */
__global__ void __launch_bounds__(NTHREADS, 1) solver_kernel(Params P)
{
    extern __shared__ char s_raw[];
    SM* sm = (SM*)s_raw;
    const int tid = threadIdx.x;
    const int gsize = gridDim.x * NTHREADS;
    const int gtid = blockIdx.x * NTHREADS + tid;
    const int warp = tid >> 5, lane = tid & 31;

    for (int i = gtid; i < DIMP; i += gsize) {
        d_x[i] = (i < DIM) ? P.x_in[i] : 0.0f;
        if (i < NB) {
            int b = P.bt[i];
            d_kp[i] = (b == 3) ? 0.f : 1.f;
            d_kq[i] = (b >= 2) ? 0.f : 1.f;
        }
    }
    gsync();

    for (int t5 = 0; t5 < 5; t5++) {
        /* ---- zero J + accumulators ---- */
        {
            size_t tot = (size_t)DIMP * LDA / 4;
            float4 z = make_float4(0.f, 0.f, 0.f, 0.f);
            for (size_t i = gtid; i < tot; i += gsize) ((float4*)d_J)[i] = z;
            for (int i = gtid; i < NB; i += gsize) { d_Pacc[i] = 0.f; d_Qacc[i] = 0.f; }
        }
        gsync();

        /* ---- edge assembly ---- */
        for (int e = gtid; e < NE; e += gsize) {
            int s = P.ei[e], d = P.ei[NE + e];
            float vm_s = d_x[NB + s], vm_d = d_x[NB + d];
            float r = P.br_r[e], xx = P.br_x[e];
            float den = r * r + xx * xx;
            float g = r / den, b = -xx / den;
            float tp = P.tap[e];
            float th = d_x[s] - d_x[d];
            float sf, cf;
            sincosf(th - P.shift[e], &sf, &cf);
            float ct = cf, st = -sf;
            float vi_t = vm_s / tp;
            float vij = vm_s * vm_d / tp;

            float gfr = P.g_fr[e], bfr = P.b_fr[e], gto = P.g_to[e], bto = P.b_to[e];
            float Pf = vi_t * vi_t * (g + gfr) + vij * (-g * cf - b * sf);
            float Qf = -vi_t * vi_t * (b + bfr) + vij * (-g * sf + b * cf);
            float Pt = vm_d * vm_d * (g + gto) + vij * (-g * ct - b * st);
            float Qt = -vm_d * vm_d * (b + bto) + vij * (-g * st + b * ct);
            atomicAdd(&d_Pacc[s], Pf); atomicAdd(&d_Pacc[d], Pt);
            atomicAdd(&d_Qacc[s], Qf); atomicAdd(&d_Qacc[d], Qt);

            float Af = g * cf + b * sf, Bf = g * sf - b * cf;
            float At = g * ct + b * st, Bt = g * st - b * ct;
            size_t Rs  = (size_t)s * LDA, Rd = (size_t)d * LDA;
            size_t Rqs = (size_t)(NB + s) * LDA, Rqd = (size_t)(NB + d) * LDA;

            if (d_kp[s] != 0.f) {
                atomicAdd(&d_J[Rs + s],      -vij * Bf);
                atomicAdd(&d_J[Rs + d],       vij * Bf);
                atomicAdd(&d_J[Rs + NB + s], -(2.f * vm_s / (tp * tp) * (g + gfr) - vm_d / tp * Af));
                atomicAdd(&d_J[Rs + NB + d],  (vm_s / tp) * Af);
            }
            if (d_kp[d] != 0.f) {
                atomicAdd(&d_J[Rd + d],      -vij * Bt);
                atomicAdd(&d_J[Rd + s],       vij * Bt);
                atomicAdd(&d_J[Rd + NB + d], -(2.f * vm_d * (g + gto) - vm_s / tp * At));
                atomicAdd(&d_J[Rd + NB + s],  (vm_d / tp) * At);
            }
            if (d_kq[s] != 0.f) {
                atomicAdd(&d_J[Rqs + s],      vij * Af);
                atomicAdd(&d_J[Rqs + d],     -vij * Af);
                atomicAdd(&d_J[Rqs + NB + s], (2.f * vm_s / (tp * tp) * (b + bfr) + vm_d / tp * Bf));
                atomicAdd(&d_J[Rqs + NB + d], (vm_s / tp) * Bf);
            }
            if (d_kq[d] != 0.f) {
                atomicAdd(&d_J[Rqd + d],      vij * At);
                atomicAdd(&d_J[Rqd + s],     -vij * At);
                atomicAdd(&d_J[Rqd + NB + d], (2.f * vm_d * (b + bto) + vm_s / tp * Bt));
                atomicAdd(&d_J[Rqd + NB + s], (vm_s / tp) * Bt);
            }
        }
        gsync();

        /* ---- diagonal terms + RHS ---- */
        for (int i = gtid; i < DIMP; i += gsize) {
            if (i < NB) {
                int b = P.bt[i];
                float vm = d_x[NB + i];
                d_J[(size_t)i * LDA + i]               += ((b == 3) ? 1.f : 0.f) + EPSJ;
                d_J[(size_t)i * LDA + NB + i]          += d_kp[i] * (-2.f * vm * P.gs[i]);
                d_J[(size_t)(NB + i) * LDA + (NB + i)] += d_kq[i] * (2.f * vm * P.bs[i]) + ((b >= 2) ? 1.f : 0.f) + EPSJ;
                d_y[i] = (b == 3) ? d_x[i] : (P.p_spec[i] - (d_Pacc[i] + vm * vm * P.gs[i]));
            } else if (i < DIM) {
                int ib = i - NB;
                float vm = d_x[i];
                d_y[i] = (P.bt[ib] >= 2) ? (vm - P.vmset[ib])
                                         : (P.q_spec[ib] - (d_Qacc[ib] - vm * vm * P.bs[ib]));
            } else {
                d_J[(size_t)i * LDA + i] = 1.0f;
                d_y[i] = 0.f;
            }
        }
        gsync();

        /* ---- blocked LU, 64-wide panels, block-0 diag lookahead ---- */
        if (blockIdx.x == 0) lu_diag(0, sm);
        gsync();
        for (int k = 0; k + 64 < DIMP; k += 64) {
            int m = DIMP - k - 64;
            /* phase A: TRSM row+col tiles */
            {
                int ntr = m / 64;
                for (int job = blockIdx.x; job < 2 * ntr; job += gridDim.x) {
                    if (job < ntr) trsm_row(k, k + 64 + job * 64, sm);
                    else           trsm_col(k, k + 64 + (job - ntr) * 64, sm);
                }
            }
            gsync();
            /* phase B: GEMM (256x128 tiles); block0 does tile(0,0) then next diag */
            {
                int gr = (m + 255) / 256;
                int gc = (m + 127) / 128;
                if (blockIdx.x == 0) {
                    gemm_tile(k, m, 0, 0, sm);
                    lu_diag(k + 64, sm);
                } else {
                    for (int job = blockIdx.x; job < gr * gc; job += gridDim.x - 1)
                        gemm_tile(k, m, (job / gc) * 256, (job % gc) * 128, sm);
                }
            }
            gsync();
        }

        /* ---- forward substitution, 128-wide panels, block-0 lookahead ---- */
        if (blockIdx.x == 0) subst_diag_fwd128(0, sm);
        gsync();
        for (int k = 0; k + PW < DIMP; k += PW) {
            __syncthreads();
            if (tid < PW) sm->sub.yc[tid] = d_y[k + tid];
            __syncthreads();
            if (blockIdx.x == 0) {
                for (int r = k + PW + warp; r < k + 2 * PW; r += NWARPS)
                    row_update(r, k, sm->sub.yc, lane);
                __syncthreads();
                subst_diag_fwd128(k + PW, sm);
            } else {
                int gw = (blockIdx.x - 1) * NWARPS + warp;
                int tot = (gridDim.x - 1) * NWARPS;
                for (int r = k + 2 * PW + gw; r < DIMP; r += tot)
                    row_update(r, k, sm->sub.yc, lane);
            }
            gsync();
        }

        /* ---- backward substitution ---- */
        if (blockIdx.x == 0) subst_diag_bwd128(DIMP - PW, sm);
        gsync();
        for (int k = DIMP - PW; k > 0; k -= PW) {
            __syncthreads();
            if (tid < PW) sm->sub.yc[tid] = d_y[k + tid];
            __syncthreads();
            if (blockIdx.x == 0) {
                for (int r = k - PW + warp; r < k; r += NWARPS)
                    row_update(r, k, sm->sub.yc, lane);
                __syncthreads();
                subst_diag_bwd128(k - PW, sm);
            } else {
                int gw = (blockIdx.x - 1) * NWARPS + warp;
                int tot = (gridDim.x - 1) * NWARPS;
                for (int r = gw; r < k - PW; r += tot)
                    row_update(r, k, sm->sub.yc, lane);
            }
            gsync();
        }

        /* ---- Newton update ---- */
        for (int i = gtid; i < DIM; i += gsize) {
            float v = d_x[i] - d_y[i];
            if (i >= NB) v = fminf(fmaxf(v, 0.5f), 1.5f);
            d_x[i] = v;
        }
        gsync();
    }

    for (int i = gtid; i < DIM; i += gsize)
        P.out[i] = d_x[i];
}

extern "C" void kernel_launch(void* const* d_in, const int* in_sizes, int n_in,
                              void* d_out, int out_size)
{
    Params P;
    P.x_in   = (const float*)d_in[0];
    P.ei     = (const int*)  d_in[1];
    P.br_r   = (const float*)d_in[2];
    P.br_x   = (const float*)d_in[3];
    P.g_fr   = (const float*)d_in[4];
    P.b_fr   = (const float*)d_in[5];
    P.g_to   = (const float*)d_in[6];
    P.b_to   = (const float*)d_in[7];
    P.tap    = (const float*)d_in[8];
    P.shift  = (const float*)d_in[9];
    P.p_spec = (const float*)d_in[10];
    P.q_spec = (const float*)d_in[11];
    P.gs     = (const float*)d_in[12];
    P.bs     = (const float*)d_in[13];
    P.bt     = (const int*)  d_in[14];
    P.vmset  = (const float*)d_in[15];
    P.out    = (float*)d_out;

    cudaFuncSetAttribute(solver_kernel,
                         cudaFuncAttributeMaxDynamicSharedMemorySize,
                         (int)SMEM_BYTES);

    int dev = 0, nsm = 0, per_sm = 0;
    cudaGetDevice(&dev);
    cudaDeviceGetAttribute(&nsm, cudaDevAttrMultiProcessorCount, dev);
    cudaOccupancyMaxActiveBlocksPerMultiprocessor(&per_sm, solver_kernel,
                                                  NTHREADS, SMEM_BYTES);
    if (per_sm < 1) per_sm = 1;
    int grid = nsm * per_sm;
    if (grid < 2) grid = 2;
    if (grid > 1024) grid = 1024;

    solver_kernel<<<grid, NTHREADS, SMEM_BYTES>>>(P);
}

// round 8
// speedup vs baseline: 1.5399x; 1.1318x over previous
#include <cuda_runtime.h>
#include <math.h>

#define EPSJ 1e-6f
#define NB   2000
#define DIM  4000
#define DIMP 4096
#define NE   6000
#define LDA  4128
#define NTHREADS 512
#define NWARPS   (NTHREADS / 32)
#define PW   128              /* backward-substitution panel width */

__device__ float d_J[(size_t)DIMP * LDA];
__device__ float d_x[DIMP];
__device__ float d_y[DIMP];
__device__ float d_Pacc[NB];
__device__ float d_Qacc[NB];
__device__ float d_kp[NB];
__device__ float d_kq[NB];
__device__ volatile unsigned d_bar_gen;
__device__ unsigned d_bar_cnt;

struct Params {
    const float* x_in; const int* ei;
    const float *br_r, *br_x, *g_fr, *b_fr, *g_to, *b_to, *tap, *shift;
    const float *p_spec, *q_spec, *gs, *bs;
    const int* bt; const float* vmset;
    float* out;
};

struct SM {
    union {
        struct { float s[64][65]; } diag;            /* col 64 carries y */
        struct { float su[64][65]; float sa[64][65]; float sinv[64]; } trsm;
        struct { float As[2][16][132]; float Bs[2][16][132]; } gemm;
        struct { float m[128][129]; float y[128]; float inv[128]; float yc[128]; } sub;
    };
};
#define SMEM_BYTES sizeof(SM)

/* ---------- f32x2 packed-FMA helpers ---------- */
__device__ __forceinline__ unsigned long long pk2(float x)
{
    unsigned long long r;
    asm("mov.b64 %0, {%1, %1};" : "=l"(r) : "f"(x));
    return r;
}
__device__ __forceinline__ void fma2(unsigned long long& d,
                                     unsigned long long a, unsigned long long b)
{
    asm("fma.rn.f32x2 %0, %1, %2, %0;" : "+l"(d) : "l"(a), "l"(b));
}
__device__ __forceinline__ float2 upk(unsigned long long v)
{
    float lo, hi;
    asm("mov.b64 {%0, %1}, %2;" : "=f"(lo), "=f"(hi) : "l"(v));
    return make_float2(lo, hi);
}

/* ---------- software grid barrier (simple, proven) ---------- */
__device__ __forceinline__ void gsync()
{
    __syncthreads();
    if (threadIdx.x == 0) {
        __threadfence();
        unsigned gen = d_bar_gen;
        if (atomicAdd(&d_bar_cnt, 1u) == gridDim.x - 1) {
            d_bar_cnt = 0;
            __threadfence();
            d_bar_gen = gen + 1;
        } else {
            while (d_bar_gen == gen) { }
            __threadfence();
        }
    }
    __syncthreads();
}

/* ---------- LU 64x64 diagonal factor (no pivot) + in-tile y solve ---------- */
__device__ void lu_diag(int k, SM* sm)
{
    float (*s)[65] = sm->diag.s;
    int tid = threadIdx.x;
    __syncthreads();
    for (int idx = tid; idx < 4096; idx += NTHREADS)
        s[idx >> 6][idx & 63] = d_J[(size_t)(k + (idx >> 6)) * LDA + k + (idx & 63)];
    if (tid < 64) s[tid][64] = d_y[k + tid];     /* y rides in the pad column */
    __syncthreads();
    int i = tid & 63, cgp = tid >> 6;
    for (int j = 0; j < 64; j++) {
        float lij = (i > j) ? s[i][j] * (1.f / s[j][j]) : 0.f;
        if (i > j)
            for (int c = cgp; c < 65; c += NTHREADS / 64)   /* includes y col */
                if (c > j) s[i][c] -= lij * s[j][c];
        __syncthreads();
    }
    for (int idx = tid; idx < 4096; idx += NTHREADS) {
        int r = idx >> 6, c = idx & 63;
        float v = s[r][c];
        if (r > c) v *= (1.f / s[c][c]);
        d_J[(size_t)(k + r) * LDA + k + c] = v;
    }
    if (tid < 64) d_y[k + tid] = s[tid][64];     /* y_k = L11^{-1} y_k */
}

/* ---------- L21 tile = A21 * U11^{-1} ---------- */
__device__ void trsm_row(int k, int r0, SM* sm)
{
    float (*su)[65] = sm->trsm.su;
    float (*sa)[65] = sm->trsm.sa;
    float* sinv = sm->trsm.sinv;
    int tid = threadIdx.x;
    __syncthreads();
    for (int idx = tid; idx < 4096; idx += NTHREADS) {
        int i = idx >> 6, j = idx & 63;
        su[i][j] = d_J[(size_t)(k + i) * LDA + k + j];
        sa[i][j] = d_J[(size_t)(r0 + i) * LDA + k + j];
    }
    __syncthreads();
    if (tid < 64) sinv[tid] = 1.f / su[tid][tid];
    __syncthreads();
    for (int idx = tid; idx < 4096; idx += NTHREADS)
        su[idx >> 6][idx & 63] *= sinv[idx >> 6];
    __syncthreads();
    int i = tid & 63, cgp = tid >> 6;
    for (int j = 0; j < 64; j++) {
        float aij = sa[i][j];
        for (int c = cgp; c < 64; c += NTHREADS / 64)
            if (c > j) sa[i][c] -= aij * su[j][c];
        __syncthreads();
    }
    for (int idx = tid; idx < 4096; idx += NTHREADS) {
        int r = idx >> 6, j = idx & 63;
        d_J[(size_t)(r0 + r) * LDA + k + j] = sa[r][j] * sinv[j];
    }
}

/* ---------- U12 tile = L11^{-1} * A12 ---------- */
__device__ void trsm_col(int k, int c0, SM* sm)
{
    float (*sl)[65] = sm->trsm.su;
    float (*sa)[65] = sm->trsm.sa;
    int tid = threadIdx.x;
    __syncthreads();
    for (int idx = tid; idx < 4096; idx += NTHREADS) {
        int i = idx >> 6, j = idx & 63;
        sl[i][j] = d_J[(size_t)(k + i) * LDA + k + j];
        sa[i][j] = d_J[(size_t)(k + i) * LDA + c0 + j];
    }
    __syncthreads();
    int c = tid & 63, rg = tid >> 6;
    for (int j = 0; j < 64; j++) {
        float ajc = sa[j][c];
        for (int i2 = rg; i2 < 64; i2 += NTHREADS / 64)
            if (i2 > j) sa[i2][c] -= sl[i2][j] * ajc;
        __syncthreads();
    }
    for (int idx = tid; idx < 4096; idx += NTHREADS)
        d_J[(size_t)(k + (idx >> 6)) * LDA + c0 + (idx & 63)] = sa[idx >> 6][idx & 63];
}

/* ---------- trailing update tile: 128x128, K=64, f32x2, double-buffered ---------- */
__device__ void gemm_tile(int k, int m, int row0, int col0, SM* sm)
{
    const int k2 = k + 64;
    const int tid = threadIdx.x;
    const int ty = tid >> 5;
    const int tx = tid & 31;
    const int ai = tid >> 2;
    const int aj = (tid & 3) << 2;
    const int bk = tid >> 5;
    const int bc = (tid & 31) << 2;
    const bool arow_ok = (row0 + ai) < m;
    const bool bcol_ok = (col0 + bc) < m;
    const float* gA = &d_J[(size_t)(k2 + row0 + ai) * LDA + k + aj];
    const float* gB = &d_J[(size_t)(k + bk) * LDA + k2 + col0 + bc];

    unsigned long long acc[4][4];
#pragma unroll
    for (int u = 0; u < 4; u++)
#pragma unroll
        for (int v = 0; v < 4; v++) acc[u][v] = 0ull;

    float4 z4 = make_float4(0.f, 0.f, 0.f, 0.f);
    float4 ra = arow_ok ? *(const float4*)gA : z4;
    float4 rb = bcol_ok ? *(const float4*)gB : z4;

    __syncthreads();
    sm->gemm.As[0][aj + 0][ai] = ra.x;
    sm->gemm.As[0][aj + 1][ai] = ra.y;
    sm->gemm.As[0][aj + 2][ai] = ra.z;
    sm->gemm.As[0][aj + 3][ai] = ra.w;
    *(float4*)&sm->gemm.Bs[0][bk][bc] = rb;
    __syncthreads();

    for (int c = 0; c < 4; c++) {
        const int cur = c & 1;
        float4 na, nb;
        if (c < 3) {
            na = arow_ok ? *(const float4*)(gA + (c + 1) * 16) : z4;
            nb = bcol_ok ? *(const float4*)(gB + (size_t)(c + 1) * 16 * LDA) : z4;
        }
#pragma unroll
        for (int kk = 0; kk < 16; kk++) {
            const unsigned long long* ap =
                (const unsigned long long*)&sm->gemm.As[cur][kk][ty * 8];
            unsigned long long a0 = ap[0], a1 = ap[1], a2 = ap[2], a3 = ap[3];
            float4 bv = *(const float4*)&sm->gemm.Bs[cur][kk][tx * 4];
            unsigned long long b0 = pk2(bv.x), b1 = pk2(bv.y),
                               b2 = pk2(bv.z), b3 = pk2(bv.w);
            fma2(acc[0][0], a0, b0); fma2(acc[0][1], a0, b1);
            fma2(acc[0][2], a0, b2); fma2(acc[0][3], a0, b3);
            fma2(acc[1][0], a1, b0); fma2(acc[1][1], a1, b1);
            fma2(acc[1][2], a1, b2); fma2(acc[1][3], a1, b3);
            fma2(acc[2][0], a2, b0); fma2(acc[2][1], a2, b1);
            fma2(acc[2][2], a2, b2); fma2(acc[2][3], a2, b3);
            fma2(acc[3][0], a3, b0); fma2(acc[3][1], a3, b1);
            fma2(acc[3][2], a3, b2); fma2(acc[3][3], a3, b3);
        }
        if (c < 3) {
            const int nxt = cur ^ 1;
            sm->gemm.As[nxt][aj + 0][ai] = na.x;
            sm->gemm.As[nxt][aj + 1][ai] = na.y;
            sm->gemm.As[nxt][aj + 2][ai] = na.z;
            sm->gemm.As[nxt][aj + 3][ai] = na.w;
            *(float4*)&sm->gemm.Bs[nxt][bk][bc] = nb;
        }
        __syncthreads();
    }

#pragma unroll
    for (int u = 0; u < 4; u++) {
        int r0 = row0 + ty * 8 + u * 2;
        if (r0 < m && (col0 + tx * 4) < m) {
            float2 p0 = upk(acc[u][0]), p1 = upk(acc[u][1]);
            float2 p2 = upk(acc[u][2]), p3 = upk(acc[u][3]);
            float4* c0 = (float4*)&d_J[(size_t)(k2 + r0) * LDA + k2 + col0 + tx * 4];
            float4 v0 = *c0;
            v0.x -= p0.x; v0.y -= p1.x; v0.z -= p2.x; v0.w -= p3.x;
            *c0 = v0;
            float4* c1 = (float4*)&d_J[(size_t)(k2 + r0 + 1) * LDA + k2 + col0 + tx * 4];
            float4 v1 = *c1;
            v1.x -= p0.y; v1.y -= p1.y; v1.z -= p2.y; v1.w -= p3.y;
            *c1 = v1;
        }
    }
}

/* ---------- forward y-update: y[r0..r1) -= L21(rows) . y_k (64-wide) ---------- */
__device__ __forceinline__ void y_update_range(int k, int r0, int r1)
{
    const int warp = threadIdx.x >> 5, lane = threadIdx.x & 31;
    const float ylo = d_y[k + lane];
    const float yhi = d_y[k + 32 + lane];
    for (int r = r0 + warp; r < r1; r += NWARPS) {
        const float* row = &d_J[(size_t)r * LDA + k];
        float s = row[lane] * ylo + row[lane + 32] * yhi;
#pragma unroll
        for (int o = 16; o; o >>= 1) s += __shfl_down_sync(0xffffffffu, s, o);
        if (lane == 0) d_y[r] -= s;
    }
}

/* ---------- 128-wide backward-substitution diagonal solve ---------- */
__device__ void subst_diag_bwd128(int k, SM* sm)
{
    int t = threadIdx.x;
    __syncthreads();
    for (int idx = t; idx < 128 * 128; idx += NTHREADS)
        sm->sub.m[idx >> 7][idx & 127] = d_J[(size_t)(k + (idx >> 7)) * LDA + k + (idx & 127)];
    if (t < 128) sm->sub.y[t] = d_y[k + t];
    __syncthreads();
    if (t < 128) sm->sub.inv[t] = 1.f / sm->sub.m[t][t];
    __syncthreads();
    for (int j = 127; j >= 0; j--) {
        float val = sm->sub.y[j] * sm->sub.inv[j];
        if (t == j) sm->sub.y[j] = val;
        else if (t < j) sm->sub.y[t] -= sm->sub.m[t][j] * val;
        __syncthreads();
    }
    if (t < 128) d_y[k + t] = sm->sub.y[t];
    __syncthreads();
}

/* ---------- one 128-wide dot for bwd substitution row update ---------- */
__device__ __forceinline__ void row_update(int r, int k, const float* yc, int lane)
{
    const float* row = &d_J[(size_t)r * LDA + k];
    float s = row[lane] * yc[lane] + row[lane + 32] * yc[lane + 32]
            + row[lane + 64] * yc[lane + 64] + row[lane + 96] * yc[lane + 96];
#pragma unroll
    for (int o = 16; o; o >>= 1) s += __shfl_down_sync(0xffffffffu, s, o);
    if (lane == 0) d_y[r] -= s;
}

/* =======================================================================
 *  The one persistent kernel
 * ======================================================================= */
__global__ void __launch_bounds__(NTHREADS, 1) solver_kernel(Params P)
{
    extern __shared__ char s_raw[];
    SM* sm = (SM*)s_raw;
    const int tid = threadIdx.x;
    const int gsize = gridDim.x * NTHREADS;
    const int gtid = blockIdx.x * NTHREADS + tid;
    const int warp = tid >> 5, lane = tid & 31;

    for (int i = gtid; i < DIMP; i += gsize) {
        d_x[i] = (i < DIM) ? P.x_in[i] : 0.0f;
        if (i < NB) {
            int b = P.bt[i];
            d_kp[i] = (b == 3) ? 0.f : 1.f;
            d_kq[i] = (b >= 2) ? 0.f : 1.f;
        }
    }
    gsync();

    for (int t5 = 0; t5 < 5; t5++) {
        /* ---- zero J + accumulators ---- */
        {
            size_t tot = (size_t)DIMP * LDA / 4;
            float4 z = make_float4(0.f, 0.f, 0.f, 0.f);
            for (size_t i = gtid; i < tot; i += gsize) ((float4*)d_J)[i] = z;
            for (int i = gtid; i < NB; i += gsize) { d_Pacc[i] = 0.f; d_Qacc[i] = 0.f; }
        }
        gsync();

        /* ---- edge assembly ---- */
        for (int e = gtid; e < NE; e += gsize) {
            int s = P.ei[e], d = P.ei[NE + e];
            float vm_s = d_x[NB + s], vm_d = d_x[NB + d];
            float r = P.br_r[e], xx = P.br_x[e];
            float den = r * r + xx * xx;
            float g = r / den, b = -xx / den;
            float tp = P.tap[e];
            float th = d_x[s] - d_x[d];
            float sf, cf;
            sincosf(th - P.shift[e], &sf, &cf);
            float ct = cf, st = -sf;
            float vi_t = vm_s / tp;
            float vij = vm_s * vm_d / tp;

            float gfr = P.g_fr[e], bfr = P.b_fr[e], gto = P.g_to[e], bto = P.b_to[e];
            float Pf = vi_t * vi_t * (g + gfr) + vij * (-g * cf - b * sf);
            float Qf = -vi_t * vi_t * (b + bfr) + vij * (-g * sf + b * cf);
            float Pt = vm_d * vm_d * (g + gto) + vij * (-g * ct - b * st);
            float Qt = -vm_d * vm_d * (b + bto) + vij * (-g * st + b * ct);
            atomicAdd(&d_Pacc[s], Pf); atomicAdd(&d_Pacc[d], Pt);
            atomicAdd(&d_Qacc[s], Qf); atomicAdd(&d_Qacc[d], Qt);

            float Af = g * cf + b * sf, Bf = g * sf - b * cf;
            float At = g * ct + b * st, Bt = g * st - b * ct;
            size_t Rs  = (size_t)s * LDA, Rd = (size_t)d * LDA;
            size_t Rqs = (size_t)(NB + s) * LDA, Rqd = (size_t)(NB + d) * LDA;

            if (d_kp[s] != 0.f) {
                atomicAdd(&d_J[Rs + s],      -vij * Bf);
                atomicAdd(&d_J[Rs + d],       vij * Bf);
                atomicAdd(&d_J[Rs + NB + s], -(2.f * vm_s / (tp * tp) * (g + gfr) - vm_d / tp * Af));
                atomicAdd(&d_J[Rs + NB + d],  (vm_s / tp) * Af);
            }
            if (d_kp[d] != 0.f) {
                atomicAdd(&d_J[Rd + d],      -vij * Bt);
                atomicAdd(&d_J[Rd + s],       vij * Bt);
                atomicAdd(&d_J[Rd + NB + d], -(2.f * vm_d * (g + gto) - vm_s / tp * At));
                atomicAdd(&d_J[Rd + NB + s],  (vm_d / tp) * At);
            }
            if (d_kq[s] != 0.f) {
                atomicAdd(&d_J[Rqs + s],      vij * Af);
                atomicAdd(&d_J[Rqs + d],     -vij * Af);
                atomicAdd(&d_J[Rqs + NB + s], (2.f * vm_s / (tp * tp) * (b + bfr) + vm_d / tp * Bf));
                atomicAdd(&d_J[Rqs + NB + d], (vm_s / tp) * Bf);
            }
            if (d_kq[d] != 0.f) {
                atomicAdd(&d_J[Rqd + d],      vij * At);
                atomicAdd(&d_J[Rqd + s],     -vij * At);
                atomicAdd(&d_J[Rqd + NB + d], (2.f * vm_d * (b + bto) + vm_s / tp * Bt));
                atomicAdd(&d_J[Rqd + NB + s], (vm_s / tp) * Bt);
            }
        }
        gsync();

        /* ---- diagonal terms + RHS ---- */
        for (int i = gtid; i < DIMP; i += gsize) {
            if (i < NB) {
                int b = P.bt[i];
                float vm = d_x[NB + i];
                d_J[(size_t)i * LDA + i]               += ((b == 3) ? 1.f : 0.f) + EPSJ;
                d_J[(size_t)i * LDA + NB + i]          += d_kp[i] * (-2.f * vm * P.gs[i]);
                d_J[(size_t)(NB + i) * LDA + (NB + i)] += d_kq[i] * (2.f * vm * P.bs[i]) + ((b >= 2) ? 1.f : 0.f) + EPSJ;
                d_y[i] = (b == 3) ? d_x[i] : (P.p_spec[i] - (d_Pacc[i] + vm * vm * P.gs[i]));
            } else if (i < DIM) {
                int ib = i - NB;
                float vm = d_x[i];
                d_y[i] = (P.bt[ib] >= 2) ? (vm - P.vmset[ib])
                                         : (P.q_spec[ib] - (d_Qacc[ib] - vm * vm * P.bs[ib]));
            } else {
                d_J[(size_t)i * LDA + i] = 1.0f;
                d_y[i] = 0.f;
            }
        }
        gsync();

        /* ---- blocked LU (fwd substitution folded in), block-0 lookahead ---- */
        if (blockIdx.x == 0) lu_diag(0, sm);       /* includes y_0 solve */
        gsync();
        for (int k = 0; k + 64 < DIMP; k += 64) {
            int m = DIMP - k - 64;
            /* phase A: TRSM row+col tiles */
            {
                int ntr = m / 64;
                for (int job = blockIdx.x; job < 2 * ntr; job += gridDim.x) {
                    if (job < ntr) trsm_row(k, k + 64 + job * 64, sm);
                    else           trsm_col(k, k + 64 + (job - ntr) * 64, sm);
                }
            }
            gsync();
            /* phase B: y-jobs + GEMM tiles; block0: y-partial, tile(0,0), next diag */
            {
                int g = (m + 127) / 128;
                int nyj = (m - 64 + 511) / 512;     /* y-update slices for rows k+128.. */
                if (blockIdx.x == 0) {
                    y_update_range(k, k + 64, k + 128);   /* y rows of next diag */
                    __syncthreads();
                    gemm_tile(k, m, 0, 0, sm);
                    lu_diag(k + 64, sm);                   /* factors + solves y_{k+64} */
                } else {
                    int njobs = nyj + g * g - 1;           /* tiles 1..g^2-1 */
                    for (int job = blockIdx.x - 1; job < njobs; job += gridDim.x - 1) {
                        if (job < nyj) {
                            int r0 = k + 128 + job * 512;
                            int r1 = r0 + 512; if (r1 > DIMP) r1 = DIMP;
                            y_update_range(k, r0, r1);
                        } else {
                            int t2 = job - nyj + 1;
                            gemm_tile(k, m, (t2 / g) * 128, (t2 % g) * 128, sm);
                        }
                    }
                }
            }
            gsync();
        }
        /* d_y now holds L^{-1} F */

        /* ---- backward substitution, 128-wide panels, block-0 lookahead ---- */
        if (blockIdx.x == 0) subst_diag_bwd128(DIMP - PW, sm);
        gsync();
        for (int k = DIMP - PW; k > 0; k -= PW) {
            __syncthreads();
            if (tid < PW) sm->sub.yc[tid] = d_y[k + tid];
            __syncthreads();
            if (blockIdx.x == 0) {
                for (int r = k - PW + warp; r < k; r += NWARPS)
                    row_update(r, k, sm->sub.yc, lane);
                __syncthreads();
                subst_diag_bwd128(k - PW, sm);
            } else {
                int gw = (blockIdx.x - 1) * NWARPS + warp;
                int tot = (gridDim.x - 1) * NWARPS;
                for (int r = gw; r < k - PW; r += tot)
                    row_update(r, k, sm->sub.yc, lane);
            }
            gsync();
        }

        /* ---- Newton update ---- */
        for (int i = gtid; i < DIM; i += gsize) {
            float v = d_x[i] - d_y[i];
            if (i >= NB) v = fminf(fmaxf(v, 0.5f), 1.5f);
            d_x[i] = v;
        }
        gsync();
    }

    for (int i = gtid; i < DIM; i += gsize)
        P.out[i] = d_x[i];
}

extern "C" void kernel_launch(void* const* d_in, const int* in_sizes, int n_in,
                              void* d_out, int out_size)
{
    Params P;
    P.x_in   = (const float*)d_in[0];
    P.ei     = (const int*)  d_in[1];
    P.br_r   = (const float*)d_in[2];
    P.br_x   = (const float*)d_in[3];
    P.g_fr   = (const float*)d_in[4];
    P.b_fr   = (const float*)d_in[5];
    P.g_to   = (const float*)d_in[6];
    P.b_to   = (const float*)d_in[7];
    P.tap    = (const float*)d_in[8];
    P.shift  = (const float*)d_in[9];
    P.p_spec = (const float*)d_in[10];
    P.q_spec = (const float*)d_in[11];
    P.gs     = (const float*)d_in[12];
    P.bs     = (const float*)d_in[13];
    P.bt     = (const int*)  d_in[14];
    P.vmset  = (const float*)d_in[15];
    P.out    = (float*)d_out;

    cudaFuncSetAttribute(solver_kernel,
                         cudaFuncAttributeMaxDynamicSharedMemorySize,
                         (int)SMEM_BYTES);

    int dev = 0, nsm = 0, per_sm = 0;
    cudaGetDevice(&dev);
    cudaDeviceGetAttribute(&nsm, cudaDevAttrMultiProcessorCount, dev);
    cudaOccupancyMaxActiveBlocksPerMultiprocessor(&per_sm, solver_kernel,
                                                  NTHREADS, SMEM_BYTES);
    if (per_sm < 1) per_sm = 1;
    int grid = nsm * per_sm;
    if (grid < 2) grid = 2;
    if (grid > 1024) grid = 1024;

    solver_kernel<<<grid, NTHREADS, SMEM_BYTES>>>(P);
}

// round 9
// speedup vs baseline: 1.5538x; 1.0091x over previous
#include <cuda_runtime.h>
#include <math.h>

#define EPSJ 1e-6f
#define NB   2000
#define DIM  4000
#define DIMP 4096
#define NE   6000
#define LDA  4128
#define NTHREADS 512
#define NWARPS   (NTHREADS / 32)
#define PW   128              /* backward-substitution panel width */

__device__ float d_J[(size_t)DIMP * LDA];
__device__ float d_x[DIMP];
__device__ float d_y[DIMP];
__device__ float d_Pacc[NB];
__device__ float d_Qacc[NB];
__device__ float d_kp[NB];
__device__ float d_kq[NB];
__device__ volatile unsigned d_bar_gen;
__device__ unsigned d_bar_cnt;
__device__ volatile unsigned d_rowflag[64];
__device__ volatile unsigned d_colflag[64];

struct Params {
    const float* x_in; const int* ei;
    const float *br_r, *br_x, *g_fr, *b_fr, *g_to, *b_to, *tap, *shift;
    const float *p_spec, *q_spec, *gs, *bs;
    const int* bt; const float* vmset;
    float* out;
};

struct SM {
    union {
        struct { float s[64][65]; } diag;            /* col 64 carries y */
        struct { float su[64][65]; float sa[64][65]; float sinv[64]; } trsm;
        struct { float As[2][16][132]; float Bs[2][16][132]; } gemm;
        struct { float m[128][129]; float y[128]; float inv[128]; float yc[128]; } sub;
    };
};
#define SMEM_BYTES sizeof(SM)

/* ---------- f32x2 packed-FMA helpers ---------- */
__device__ __forceinline__ unsigned long long pk2(float x)
{
    unsigned long long r;
    asm("mov.b64 %0, {%1, %1};" : "=l"(r) : "f"(x));
    return r;
}
__device__ __forceinline__ void fma2(unsigned long long& d,
                                     unsigned long long a, unsigned long long b)
{
    asm("fma.rn.f32x2 %0, %1, %2, %0;" : "+l"(d) : "l"(a), "l"(b));
}
__device__ __forceinline__ float2 upk(unsigned long long v)
{
    float lo, hi;
    asm("mov.b64 {%0, %1}, %2;" : "=f"(lo), "=f"(hi) : "l"(v));
    return make_float2(lo, hi);
}

/* ---------- software grid barrier (simple, proven) ---------- */
__device__ __forceinline__ void gsync()
{
    __syncthreads();
    if (threadIdx.x == 0) {
        __threadfence();
        unsigned gen = d_bar_gen;
        if (atomicAdd(&d_bar_cnt, 1u) == gridDim.x - 1) {
            d_bar_cnt = 0;
            __threadfence();
            d_bar_gen = gen + 1;
        } else {
            while (d_bar_gen == gen) { }
            __threadfence();
        }
    }
    __syncthreads();
}

/* ---------- LU 64x64 diagonal factor (no pivot) + in-tile y solve ---------- */
__device__ void lu_diag(int k, SM* sm)
{
    float (*s)[65] = sm->diag.s;
    int tid = threadIdx.x;
    __syncthreads();
    for (int idx = tid; idx < 4096; idx += NTHREADS)
        s[idx >> 6][idx & 63] = d_J[(size_t)(k + (idx >> 6)) * LDA + k + (idx & 63)];
    if (tid < 64) s[tid][64] = d_y[k + tid];     /* y rides in the pad column */
    __syncthreads();
    int i = tid & 63, cgp = tid >> 6;
    for (int j = 0; j < 64; j++) {
        float lij = (i > j) ? s[i][j] * (1.f / s[j][j]) : 0.f;
        if (i > j)
            for (int c = cgp; c < 65; c += NTHREADS / 64)   /* includes y col */
                if (c > j) s[i][c] -= lij * s[j][c];
        __syncthreads();
    }
    for (int idx = tid; idx < 4096; idx += NTHREADS) {
        int r = idx >> 6, c = idx & 63;
        float v = s[r][c];
        if (r > c) v *= (1.f / s[c][c]);
        d_J[(size_t)(k + r) * LDA + k + c] = v;
    }
    if (tid < 64) d_y[k + tid] = s[tid][64];     /* y_k = L11^{-1} y_k */
}

/* ---------- L21 tile = A21 * U11^{-1} ---------- */
__device__ void trsm_row(int k, int r0, SM* sm)
{
    float (*su)[65] = sm->trsm.su;
    float (*sa)[65] = sm->trsm.sa;
    float* sinv = sm->trsm.sinv;
    int tid = threadIdx.x;
    __syncthreads();
    for (int idx = tid; idx < 4096; idx += NTHREADS) {
        int i = idx >> 6, j = idx & 63;
        su[i][j] = d_J[(size_t)(k + i) * LDA + k + j];
        sa[i][j] = d_J[(size_t)(r0 + i) * LDA + k + j];
    }
    __syncthreads();
    if (tid < 64) sinv[tid] = 1.f / su[tid][tid];
    __syncthreads();
    for (int idx = tid; idx < 4096; idx += NTHREADS)
        su[idx >> 6][idx & 63] *= sinv[idx >> 6];
    __syncthreads();
    int i = tid & 63, cgp = tid >> 6;
    for (int j = 0; j < 64; j++) {
        float aij = sa[i][j];
        for (int c = cgp; c < 64; c += NTHREADS / 64)
            if (c > j) sa[i][c] -= aij * su[j][c];
        __syncthreads();
    }
    for (int idx = tid; idx < 4096; idx += NTHREADS) {
        int r = idx >> 6, j = idx & 63;
        d_J[(size_t)(r0 + r) * LDA + k + j] = sa[r][j] * sinv[j];
    }
}

/* ---------- U12 tile = L11^{-1} * A12 ---------- */
__device__ void trsm_col(int k, int c0, SM* sm)
{
    float (*sl)[65] = sm->trsm.su;
    float (*sa)[65] = sm->trsm.sa;
    int tid = threadIdx.x;
    __syncthreads();
    for (int idx = tid; idx < 4096; idx += NTHREADS) {
        int i = idx >> 6, j = idx & 63;
        sl[i][j] = d_J[(size_t)(k + i) * LDA + k + j];
        sa[i][j] = d_J[(size_t)(k + i) * LDA + c0 + j];
    }
    __syncthreads();
    int c = tid & 63, rg = tid >> 6;
    for (int j = 0; j < 64; j++) {
        float ajc = sa[j][c];
        for (int i2 = rg; i2 < 64; i2 += NTHREADS / 64)
            if (i2 > j) sa[i2][c] -= sl[i2][j] * ajc;
        __syncthreads();
    }
    for (int idx = tid; idx < 4096; idx += NTHREADS)
        d_J[(size_t)(k + (idx >> 6)) * LDA + c0 + (idx & 63)] = sa[idx >> 6][idx & 63];
}

/* ---------- trailing update tile: 128x128, K=64, f32x2, double-buffered ---------- */
__device__ void gemm_tile(int k, int m, int row0, int col0, SM* sm)
{
    const int k2 = k + 64;
    const int tid = threadIdx.x;
    const int ty = tid >> 5;
    const int tx = tid & 31;
    const int ai = tid >> 2;
    const int aj = (tid & 3) << 2;
    const int bk = tid >> 5;
    const int bc = (tid & 31) << 2;
    const bool arow_ok = (row0 + ai) < m;
    const bool bcol_ok = (col0 + bc) < m;
    const float* gA = &d_J[(size_t)(k2 + row0 + ai) * LDA + k + aj];
    const float* gB = &d_J[(size_t)(k + bk) * LDA + k2 + col0 + bc];

    unsigned long long acc[4][4];
#pragma unroll
    for (int u = 0; u < 4; u++)
#pragma unroll
        for (int v = 0; v < 4; v++) acc[u][v] = 0ull;

    float4 z4 = make_float4(0.f, 0.f, 0.f, 0.f);
    float4 ra = arow_ok ? *(const float4*)gA : z4;
    float4 rb = bcol_ok ? *(const float4*)gB : z4;

    __syncthreads();
    sm->gemm.As[0][aj + 0][ai] = ra.x;
    sm->gemm.As[0][aj + 1][ai] = ra.y;
    sm->gemm.As[0][aj + 2][ai] = ra.z;
    sm->gemm.As[0][aj + 3][ai] = ra.w;
    *(float4*)&sm->gemm.Bs[0][bk][bc] = rb;
    __syncthreads();

    for (int c = 0; c < 4; c++) {
        const int cur = c & 1;
        float4 na, nb;
        if (c < 3) {
            na = arow_ok ? *(const float4*)(gA + (c + 1) * 16) : z4;
            nb = bcol_ok ? *(const float4*)(gB + (size_t)(c + 1) * 16 * LDA) : z4;
        }
#pragma unroll
        for (int kk = 0; kk < 16; kk++) {
            const unsigned long long* ap =
                (const unsigned long long*)&sm->gemm.As[cur][kk][ty * 8];
            unsigned long long a0 = ap[0], a1 = ap[1], a2 = ap[2], a3 = ap[3];
            float4 bv = *(const float4*)&sm->gemm.Bs[cur][kk][tx * 4];
            unsigned long long b0 = pk2(bv.x), b1 = pk2(bv.y),
                               b2 = pk2(bv.z), b3 = pk2(bv.w);
            fma2(acc[0][0], a0, b0); fma2(acc[0][1], a0, b1);
            fma2(acc[0][2], a0, b2); fma2(acc[0][3], a0, b3);
            fma2(acc[1][0], a1, b0); fma2(acc[1][1], a1, b1);
            fma2(acc[1][2], a1, b2); fma2(acc[1][3], a1, b3);
            fma2(acc[2][0], a2, b0); fma2(acc[2][1], a2, b1);
            fma2(acc[2][2], a2, b2); fma2(acc[2][3], a2, b3);
            fma2(acc[3][0], a3, b0); fma2(acc[3][1], a3, b1);
            fma2(acc[3][2], a3, b2); fma2(acc[3][3], a3, b3);
        }
        if (c < 3) {
            const int nxt = cur ^ 1;
            sm->gemm.As[nxt][aj + 0][ai] = na.x;
            sm->gemm.As[nxt][aj + 1][ai] = na.y;
            sm->gemm.As[nxt][aj + 2][ai] = na.z;
            sm->gemm.As[nxt][aj + 3][ai] = na.w;
            *(float4*)&sm->gemm.Bs[nxt][bk][bc] = nb;
        }
        __syncthreads();
    }

#pragma unroll
    for (int u = 0; u < 4; u++) {
        int r0 = row0 + ty * 8 + u * 2;
        if (r0 < m && (col0 + tx * 4) < m) {
            float2 p0 = upk(acc[u][0]), p1 = upk(acc[u][1]);
            float2 p2 = upk(acc[u][2]), p3 = upk(acc[u][3]);
            float4* c0 = (float4*)&d_J[(size_t)(k2 + r0) * LDA + k2 + col0 + tx * 4];
            float4 v0 = *c0;
            v0.x -= p0.x; v0.y -= p1.x; v0.z -= p2.x; v0.w -= p3.x;
            *c0 = v0;
            float4* c1 = (float4*)&d_J[(size_t)(k2 + r0 + 1) * LDA + k2 + col0 + tx * 4];
            float4 v1 = *c1;
            v1.x -= p0.y; v1.y -= p1.y; v1.z -= p2.y; v1.w -= p3.y;
            *c1 = v1;
        }
    }
}

/* ---------- forward y-update: y[r0..r1) -= L21(rows) . y_k (64-wide) ---------- */
__device__ __forceinline__ void y_update_range(int k, int r0, int r1)
{
    const int warp = threadIdx.x >> 5, lane = threadIdx.x & 31;
    const float ylo = d_y[k + lane];
    const float yhi = d_y[k + 32 + lane];
    for (int r = r0 + warp; r < r1; r += NWARPS) {
        const float* row = &d_J[(size_t)r * LDA + k];
        float s = row[lane] * ylo + row[lane + 32] * yhi;
#pragma unroll
        for (int o = 16; o; o >>= 1) s += __shfl_down_sync(0xffffffffu, s, o);
        if (lane == 0) d_y[r] -= s;
    }
}

/* ---------- flag helpers ---------- */
__device__ __forceinline__ void wait_flag(volatile unsigned* f, unsigned epoch)
{
    while (*f != epoch) { }
}

/* ---------- 128-wide backward-substitution diagonal solve ---------- */
__device__ void subst_diag_bwd128(int k, SM* sm)
{
    int t = threadIdx.x;
    __syncthreads();
    for (int idx = t; idx < 128 * 128; idx += NTHREADS)
        sm->sub.m[idx >> 7][idx & 127] = d_J[(size_t)(k + (idx >> 7)) * LDA + k + (idx & 127)];
    if (t < 128) sm->sub.y[t] = d_y[k + t];
    __syncthreads();
    if (t < 128) sm->sub.inv[t] = 1.f / sm->sub.m[t][t];
    __syncthreads();
    for (int j = 127; j >= 0; j--) {
        float val = sm->sub.y[j] * sm->sub.inv[j];
        if (t == j) sm->sub.y[j] = val;
        else if (t < j) sm->sub.y[t] -= sm->sub.m[t][j] * val;
        __syncthreads();
    }
    if (t < 128) d_y[k + t] = sm->sub.y[t];
    __syncthreads();
}

/* ---------- one 128-wide dot for bwd substitution row update ---------- */
__device__ __forceinline__ void row_update(int r, int k, const float* yc, int lane)
{
    const float* row = &d_J[(size_t)r * LDA + k];
    float s = row[lane] * yc[lane] + row[lane + 32] * yc[lane + 32]
            + row[lane + 64] * yc[lane + 64] + row[lane + 96] * yc[lane + 96];
#pragma unroll
    for (int o = 16; o; o >>= 1) s += __shfl_down_sync(0xffffffffu, s, o);
    if (lane == 0) d_y[r] -= s;
}

/* =======================================================================
 *  The one persistent kernel
 * ======================================================================= */
__global__ void __launch_bounds__(NTHREADS, 1) solver_kernel(Params P)
{
    extern __shared__ char s_raw[];
    SM* sm = (SM*)s_raw;
    const int tid = threadIdx.x;
    const int gsize = gridDim.x * NTHREADS;
    const int gtid = blockIdx.x * NTHREADS + tid;
    const int warp = tid >> 5, lane = tid & 31;

    for (int i = gtid; i < DIMP; i += gsize) {
        d_x[i] = (i < DIM) ? P.x_in[i] : 0.0f;
        if (i < NB) {
            int b = P.bt[i];
            d_kp[i] = (b == 3) ? 0.f : 1.f;
            d_kq[i] = (b >= 2) ? 0.f : 1.f;
        }
        if (i < 64) { d_rowflag[i] = 0u; d_colflag[i] = 0u; }
    }
    gsync();

    for (int t5 = 0; t5 < 5; t5++) {
        /* ---- zero J + accumulators ---- */
        {
            size_t tot = (size_t)DIMP * LDA / 4;
            float4 z = make_float4(0.f, 0.f, 0.f, 0.f);
            for (size_t i = gtid; i < tot; i += gsize) ((float4*)d_J)[i] = z;
            for (int i = gtid; i < NB; i += gsize) { d_Pacc[i] = 0.f; d_Qacc[i] = 0.f; }
        }
        gsync();

        /* ---- edge assembly ---- */
        for (int e = gtid; e < NE; e += gsize) {
            int s = P.ei[e], d = P.ei[NE + e];
            float vm_s = d_x[NB + s], vm_d = d_x[NB + d];
            float r = P.br_r[e], xx = P.br_x[e];
            float den = r * r + xx * xx;
            float g = r / den, b = -xx / den;
            float tp = P.tap[e];
            float th = d_x[s] - d_x[d];
            float sf, cf;
            sincosf(th - P.shift[e], &sf, &cf);
            float ct = cf, st = -sf;
            float vi_t = vm_s / tp;
            float vij = vm_s * vm_d / tp;

            float gfr = P.g_fr[e], bfr = P.b_fr[e], gto = P.g_to[e], bto = P.b_to[e];
            float Pf = vi_t * vi_t * (g + gfr) + vij * (-g * cf - b * sf);
            float Qf = -vi_t * vi_t * (b + bfr) + vij * (-g * sf + b * cf);
            float Pt = vm_d * vm_d * (g + gto) + vij * (-g * ct - b * st);
            float Qt = -vm_d * vm_d * (b + bto) + vij * (-g * st + b * ct);
            atomicAdd(&d_Pacc[s], Pf); atomicAdd(&d_Pacc[d], Pt);
            atomicAdd(&d_Qacc[s], Qf); atomicAdd(&d_Qacc[d], Qt);

            float Af = g * cf + b * sf, Bf = g * sf - b * cf;
            float At = g * ct + b * st, Bt = g * st - b * ct;
            size_t Rs  = (size_t)s * LDA, Rd = (size_t)d * LDA;
            size_t Rqs = (size_t)(NB + s) * LDA, Rqd = (size_t)(NB + d) * LDA;

            if (d_kp[s] != 0.f) {
                atomicAdd(&d_J[Rs + s],      -vij * Bf);
                atomicAdd(&d_J[Rs + d],       vij * Bf);
                atomicAdd(&d_J[Rs + NB + s], -(2.f * vm_s / (tp * tp) * (g + gfr) - vm_d / tp * Af));
                atomicAdd(&d_J[Rs + NB + d],  (vm_s / tp) * Af);
            }
            if (d_kp[d] != 0.f) {
                atomicAdd(&d_J[Rd + d],      -vij * Bt);
                atomicAdd(&d_J[Rd + s],       vij * Bt);
                atomicAdd(&d_J[Rd + NB + d], -(2.f * vm_d * (g + gto) - vm_s / tp * At));
                atomicAdd(&d_J[Rd + NB + s],  (vm_d / tp) * At);
            }
            if (d_kq[s] != 0.f) {
                atomicAdd(&d_J[Rqs + s],      vij * Af);
                atomicAdd(&d_J[Rqs + d],     -vij * Af);
                atomicAdd(&d_J[Rqs + NB + s], (2.f * vm_s / (tp * tp) * (b + bfr) + vm_d / tp * Bf));
                atomicAdd(&d_J[Rqs + NB + d], (vm_s / tp) * Bf);
            }
            if (d_kq[d] != 0.f) {
                atomicAdd(&d_J[Rqd + d],      vij * At);
                atomicAdd(&d_J[Rqd + s],     -vij * At);
                atomicAdd(&d_J[Rqd + NB + d], (2.f * vm_d * (b + bto) + vm_s / tp * Bt));
                atomicAdd(&d_J[Rqd + NB + s], (vm_s / tp) * Bt);
            }
        }
        gsync();

        /* ---- diagonal terms + RHS ---- */
        for (int i = gtid; i < DIMP; i += gsize) {
            if (i < NB) {
                int b = P.bt[i];
                float vm = d_x[NB + i];
                d_J[(size_t)i * LDA + i]               += ((b == 3) ? 1.f : 0.f) + EPSJ;
                d_J[(size_t)i * LDA + NB + i]          += d_kp[i] * (-2.f * vm * P.gs[i]);
                d_J[(size_t)(NB + i) * LDA + (NB + i)] += d_kq[i] * (2.f * vm * P.bs[i]) + ((b >= 2) ? 1.f : 0.f) + EPSJ;
                d_y[i] = (b == 3) ? d_x[i] : (P.p_spec[i] - (d_Pacc[i] + vm * vm * P.gs[i]));
            } else if (i < DIM) {
                int ib = i - NB;
                float vm = d_x[i];
                d_y[i] = (P.bt[ib] >= 2) ? (vm - P.vmset[ib])
                                         : (P.q_spec[ib] - (d_Qacc[ib] - vm * vm * P.bs[ib]));
            } else {
                d_J[(size_t)i * LDA + i] = 1.0f;
                d_y[i] = 0.f;
            }
        }
        gsync();

        /* ---- blocked LU (fwd subst folded), single phase per panel ----
         * Dedicated blocks 1..2*ntr each do ONE TRSM tile first (doorbell flag),
         * then join the pool. Pool jobs (y-updates + GEMM tiles) wait on the
         * flags they need. Block 0 runs the critical chain: wait flags ->
         * y rows of next diag -> tile(0,0) -> factor next diag.           */
        if (blockIdx.x == 0) lu_diag(0, sm);       /* includes y_0 solve */
        gsync();
        for (int k = 0; k + 64 < DIMP; k += 64) {
            const int m = DIMP - k - 64;
            const int ntr = m / 64;
            const int g = (m + 127) / 128;
            const unsigned epoch = (unsigned)(t5 * 64 + (k >> 6) + 1);
            const int bid = blockIdx.x;

            if (bid == 0) {
                if (tid == 0) {
                    wait_flag(&d_rowflag[0], epoch);
                    if (ntr > 1) wait_flag(&d_rowflag[1], epoch);
                    wait_flag(&d_colflag[0], epoch);
                    if (ntr > 1) wait_flag(&d_colflag[1], epoch);
                    __threadfence();
                }
                __syncthreads();
                y_update_range(k, k + 64, k + 128);   /* y rows of next diag */
                __syncthreads();
                gemm_tile(k, m, 0, 0, sm);
                lu_diag(k + 64, sm);                   /* factors + solves y_{k+64} */
            } else {
                /* dedicated TRSM jobs: each is a block's FIRST work item */
                for (int j = bid - 1; j < 2 * ntr; j += gridDim.x - 1) {
                    if (j < ntr) {
                        trsm_row(k, k + 64 + j * 64, sm);
                        __syncthreads();
                        if (tid == 0) { __threadfence(); d_rowflag[j] = epoch; }
                    } else {
                        int i2 = j - ntr;
                        trsm_col(k, k + 64 + i2 * 64, sm);
                        __syncthreads();
                        if (tid == 0) { __threadfence(); d_colflag[i2] = epoch; }
                    }
                }
                /* pool: y-update row-tiles 1..ntr-1, then GEMM tiles 1..g*g-1 */
                const int nyj = ntr - 1;
                const int njobs = nyj + g * g - 1;
                for (int job = bid - 1; job < njobs; job += gridDim.x - 1) {
                    if (job < nyj) {
                        int rt = job + 1;
                        if (tid == 0) { wait_flag(&d_rowflag[rt], epoch); __threadfence(); }
                        __syncthreads();
                        int r0 = k + 64 + rt * 64;
                        y_update_range(k, r0, r0 + 64);
                    } else {
                        int t2 = job - nyj + 1;
                        int r = t2 / g, c = t2 % g;
                        if (tid == 0) {
                            wait_flag(&d_rowflag[2 * r], epoch);
                            if (2 * r + 1 < ntr) wait_flag(&d_rowflag[2 * r + 1], epoch);
                            wait_flag(&d_colflag[2 * c], epoch);
                            if (2 * c + 1 < ntr) wait_flag(&d_colflag[2 * c + 1], epoch);
                            __threadfence();
                        }
                        __syncthreads();
                        gemm_tile(k, m, r * 128, c * 128, sm);
                    }
                }
            }
            gsync();
        }
        /* d_y now holds L^{-1} F */

        /* ---- backward substitution, 128-wide panels, block-0 lookahead ---- */
        if (blockIdx.x == 0) subst_diag_bwd128(DIMP - PW, sm);
        gsync();
        for (int k = DIMP - PW; k > 0; k -= PW) {
            __syncthreads();
            if (tid < PW) sm->sub.yc[tid] = d_y[k + tid];
            __syncthreads();
            if (blockIdx.x == 0) {
                for (int r = k - PW + warp; r < k; r += NWARPS)
                    row_update(r, k, sm->sub.yc, lane);
                __syncthreads();
                subst_diag_bwd128(k - PW, sm);
            } else {
                int gw = (blockIdx.x - 1) * NWARPS + warp;
                int tot = (gridDim.x - 1) * NWARPS;
                for (int r = gw; r < k - PW; r += tot)
                    row_update(r, k, sm->sub.yc, lane);
            }
            gsync();
        }

        /* ---- Newton update ---- */
        for (int i = gtid; i < DIM; i += gsize) {
            float v = d_x[i] - d_y[i];
            if (i >= NB) v = fminf(fmaxf(v, 0.5f), 1.5f);
            d_x[i] = v;
        }
        gsync();
    }

    for (int i = gtid; i < DIM; i += gsize)
        P.out[i] = d_x[i];
}

extern "C" void kernel_launch(void* const* d_in, const int* in_sizes, int n_in,
                              void* d_out, int out_size)
{
    Params P;
    P.x_in   = (const float*)d_in[0];
    P.ei     = (const int*)  d_in[1];
    P.br_r   = (const float*)d_in[2];
    P.br_x   = (const float*)d_in[3];
    P.g_fr   = (const float*)d_in[4];
    P.b_fr   = (const float*)d_in[5];
    P.g_to   = (const float*)d_in[6];
    P.b_to   = (const float*)d_in[7];
    P.tap    = (const float*)d_in[8];
    P.shift  = (const float*)d_in[9];
    P.p_spec = (const float*)d_in[10];
    P.q_spec = (const float*)d_in[11];
    P.gs     = (const float*)d_in[12];
    P.bs     = (const float*)d_in[13];
    P.bt     = (const int*)  d_in[14];
    P.vmset  = (const float*)d_in[15];
    P.out    = (float*)d_out;

    cudaFuncSetAttribute(solver_kernel,
                         cudaFuncAttributeMaxDynamicSharedMemorySize,
                         (int)SMEM_BYTES);

    int dev = 0, nsm = 0, per_sm = 0;
    cudaGetDevice(&dev);
    cudaDeviceGetAttribute(&nsm, cudaDevAttrMultiProcessorCount, dev);
    cudaOccupancyMaxActiveBlocksPerMultiprocessor(&per_sm, solver_kernel,
                                                  NTHREADS, SMEM_BYTES);
    if (per_sm < 1) per_sm = 1;
    int grid = nsm * per_sm;
    if (grid < 4) grid = 4;
    if (grid > 1024) grid = 1024;

    solver_kernel<<<grid, NTHREADS, SMEM_BYTES>>>(P);
}

// round 10
// speedup vs baseline: 1.6849x; 1.0843x over previous
#include <cuda_runtime.h>
#include <math.h>

#define EPSJ 1e-6f
#define NB   2000
#define DIM  4000
#define DIMP 4096
#define NE   6000
#define LDA  4128
#define NTHREADS 512
#define NWARPS   (NTHREADS / 32)
#define PW   128              /* backward-substitution panel width */

__device__ float d_J[(size_t)DIMP * LDA];
__device__ float d_x[DIMP];
__device__ float d_y[DIMP];
__device__ float d_Pacc[NB];
__device__ float d_Qacc[NB];
__device__ float d_kp[NB];
__device__ float d_kq[NB];
__device__ volatile unsigned d_bar_gen;
__device__ volatile unsigned d_arrive[1024];
__device__ volatile unsigned d_rowflag[64];
__device__ volatile unsigned d_colflag[64];

struct Params {
    const float* x_in; const int* ei;
    const float *br_r, *br_x, *g_fr, *b_fr, *g_to, *b_to, *tap, *shift;
    const float *p_spec, *q_spec, *gs, *bs;
    const int* bt; const float* vmset;
    float* out;
};

struct SM {
    union {
        struct { float s[64][65]; } diag;            /* col 64 carries y */
        struct { float su[64][65]; float sa[64][65]; float sinv[64]; } trsm;
        struct { float As[2][16][132]; float Bs[2][16][132]; } gemm;
        struct { float A[64][65]; float B[64][132]; } g64;
        struct { float m[128][129]; float val[128]; float yc[128]; } sub;
    };
};
#define SMEM_BYTES sizeof(SM)

/* ---------- f32x2 packed-FMA helpers ---------- */
__device__ __forceinline__ unsigned long long pk2(float x)
{
    unsigned long long r;
    asm("mov.b64 %0, {%1, %1};" : "=l"(r) : "f"(x));
    return r;
}
__device__ __forceinline__ void fma2(unsigned long long& d,
                                     unsigned long long a, unsigned long long b)
{
    asm("fma.rn.f32x2 %0, %1, %2, %0;" : "+l"(d) : "l"(a), "l"(b));
}
__device__ __forceinline__ float2 upk(unsigned long long v)
{
    float lo, hi;
    asm("mov.b64 {%0, %1}, %2;" : "=f"(lo), "=f"(hi) : "l"(v));
    return make_float2(lo, hi);
}

/* ---------- flag-array grid barrier: parallel arrivals, block-0 collector.
 * Epoch-stamped, never reset; stale values from a prior launch equal the
 * final generation count, which never collides with in-run generations. */
__device__ __forceinline__ void gsync(unsigned gen)
{
    __syncthreads();
    if (blockIdx.x == 0) {
        __threadfence();
        for (int b = threadIdx.x + 1; b < (int)gridDim.x; b += NTHREADS)
            while (d_arrive[b] != gen) { }
        __threadfence();
        __syncthreads();
        if (threadIdx.x == 0) d_bar_gen = gen;
    } else {
        if (threadIdx.x == 0) {
            __threadfence();
            d_arrive[blockIdx.x] = gen;
            while (d_bar_gen != gen) { }
            __threadfence();
        }
    }
    __syncthreads();
}

__device__ __forceinline__ void wait_flag(volatile unsigned* f, unsigned epoch)
{
    while (*f != epoch) { }
}

/* ---------- LU 64x64 diagonal factor (no pivot) + in-tile y solve ---------- */
__device__ void lu_diag(int k, SM* sm)
{
    float (*s)[65] = sm->diag.s;
    int tid = threadIdx.x;
    __syncthreads();
    for (int idx = tid; idx < 4096; idx += NTHREADS)
        s[idx >> 6][idx & 63] = d_J[(size_t)(k + (idx >> 6)) * LDA + k + (idx & 63)];
    if (tid < 64) s[tid][64] = d_y[k + tid];
    __syncthreads();
    int i = tid & 63, cgp = tid >> 6;
    for (int j = 0; j < 64; j++) {
        float lij = (i > j) ? s[i][j] * (1.f / s[j][j]) : 0.f;
        if (i > j)
            for (int c = cgp; c < 65; c += NTHREADS / 64)
                if (c > j) s[i][c] -= lij * s[j][c];
        __syncthreads();
    }
    for (int idx = tid; idx < 4096; idx += NTHREADS) {
        int r = idx >> 6, c = idx & 63;
        float v = s[r][c];
        if (r > c) v *= (1.f / s[c][c]);
        d_J[(size_t)(k + r) * LDA + k + c] = v;
    }
    if (tid < 64) d_y[k + tid] = s[tid][64];
}

/* ---------- L21 tile = A21 * U11^{-1} ---------- */
__device__ void trsm_row(int k, int r0, SM* sm)
{
    float (*su)[65] = sm->trsm.su;
    float (*sa)[65] = sm->trsm.sa;
    float* sinv = sm->trsm.sinv;
    int tid = threadIdx.x;
    __syncthreads();
    for (int idx = tid; idx < 4096; idx += NTHREADS) {
        int i = idx >> 6, j = idx & 63;
        su[i][j] = d_J[(size_t)(k + i) * LDA + k + j];
        sa[i][j] = d_J[(size_t)(r0 + i) * LDA + k + j];
    }
    __syncthreads();
    if (tid < 64) sinv[tid] = 1.f / su[tid][tid];
    __syncthreads();
    for (int idx = tid; idx < 4096; idx += NTHREADS)
        su[idx >> 6][idx & 63] *= sinv[idx >> 6];
    __syncthreads();
    int i = tid & 63, cgp = tid >> 6;
    for (int j = 0; j < 64; j++) {
        float aij = sa[i][j];
        for (int c = cgp; c < 64; c += NTHREADS / 64)
            if (c > j) sa[i][c] -= aij * su[j][c];
        __syncthreads();
    }
    for (int idx = tid; idx < 4096; idx += NTHREADS) {
        int r = idx >> 6, j = idx & 63;
        d_J[(size_t)(r0 + r) * LDA + k + j] = sa[r][j] * sinv[j];
    }
}

/* ---------- U12 tile = L11^{-1} * A12 ---------- */
__device__ void trsm_col(int k, int c0, SM* sm)
{
    float (*sl)[65] = sm->trsm.su;
    float (*sa)[65] = sm->trsm.sa;
    int tid = threadIdx.x;
    __syncthreads();
    for (int idx = tid; idx < 4096; idx += NTHREADS) {
        int i = idx >> 6, j = idx & 63;
        sl[i][j] = d_J[(size_t)(k + i) * LDA + k + j];
        sa[i][j] = d_J[(size_t)(k + i) * LDA + c0 + j];
    }
    __syncthreads();
    int c = tid & 63, rg = tid >> 6;
    for (int j = 0; j < 64; j++) {
        float ajc = sa[j][c];
        for (int i2 = rg; i2 < 64; i2 += NTHREADS / 64)
            if (i2 > j) sa[i2][c] -= sl[i2][j] * ajc;
        __syncthreads();
    }
    for (int idx = tid; idx < 4096; idx += NTHREADS)
        d_J[(size_t)(k + (idx >> 6)) * LDA + c0 + (idx & 63)] = sa[idx >> 6][idx & 63];
}

/* ---------- small trailing tile: 64 rows x NCOLS cols, K=64 ---------- */
template <int NCOLS>
__device__ void gemm_block64(int k, int row0, int col0, SM* sm)
{
    const int tid = threadIdx.x;
    float (*A)[65]  = sm->g64.A;
    float (*B)[132] = sm->g64.B;
    __syncthreads();
    for (int idx = tid; idx < 4096; idx += NTHREADS) {
        int r = idx >> 6, c = idx & 63;
        A[c][r] = d_J[(size_t)(k + 64 + row0 + r) * LDA + k + c];
    }
    for (int idx = tid; idx < 64 * NCOLS; idx += NTHREADS) {
        int kk = idx / NCOLS, c = idx % NCOLS;
        B[kk][c] = d_J[(size_t)(k + kk) * LDA + (k + 64 + col0 + c)];
    }
    __syncthreads();
    constexpr int W = NCOLS / 16;
    const int rp = (tid >> 4) * 2;
    const int ct = (tid & 15) * W;
    float acc0[W], acc1[W];
#pragma unroll
    for (int v = 0; v < W; v++) { acc0[v] = 0.f; acc1[v] = 0.f; }
    for (int kk = 0; kk < 64; kk++) {
        float a0 = A[kk][rp], a1 = A[kk][rp + 1];
#pragma unroll
        for (int v = 0; v < W; v++) {
            float b = B[kk][ct + v];
            acc0[v] += a0 * b;
            acc1[v] += a1 * b;
        }
    }
    size_t base = (size_t)(k + 64 + row0 + rp) * LDA + (k + 64 + col0 + ct);
#pragma unroll
    for (int v = 0; v < W; v++) {
        d_J[base + v]       -= acc0[v];
        d_J[base + LDA + v] -= acc1[v];
    }
}

/* ---------- trailing update tile: 128x128, K=64, f32x2, double-buffered ---------- */
__device__ void gemm_tile(int k, int m, int row0, int col0, SM* sm)
{
    const int k2 = k + 64;
    const int tid = threadIdx.x;
    const int ty = tid >> 5;
    const int tx = tid & 31;
    const int ai = tid >> 2;
    const int aj = (tid & 3) << 2;
    const int bk = tid >> 5;
    const int bc = (tid & 31) << 2;
    const bool arow_ok = (row0 + ai) < m;
    const bool bcol_ok = (col0 + bc) < m;
    const float* gA = &d_J[(size_t)(k2 + row0 + ai) * LDA + k + aj];
    const float* gB = &d_J[(size_t)(k + bk) * LDA + k2 + col0 + bc];

    unsigned long long acc[4][4];
#pragma unroll
    for (int u = 0; u < 4; u++)
#pragma unroll
        for (int v = 0; v < 4; v++) acc[u][v] = 0ull;

    float4 z4 = make_float4(0.f, 0.f, 0.f, 0.f);
    float4 ra = arow_ok ? *(const float4*)gA : z4;
    float4 rb = bcol_ok ? *(const float4*)gB : z4;

    __syncthreads();
    sm->gemm.As[0][aj + 0][ai] = ra.x;
    sm->gemm.As[0][aj + 1][ai] = ra.y;
    sm->gemm.As[0][aj + 2][ai] = ra.z;
    sm->gemm.As[0][aj + 3][ai] = ra.w;
    *(float4*)&sm->gemm.Bs[0][bk][bc] = rb;
    __syncthreads();

    for (int c = 0; c < 4; c++) {
        const int cur = c & 1;
        float4 na, nb;
        if (c < 3) {
            na = arow_ok ? *(const float4*)(gA + (c + 1) * 16) : z4;
            nb = bcol_ok ? *(const float4*)(gB + (size_t)(c + 1) * 16 * LDA) : z4;
        }
#pragma unroll
        for (int kk = 0; kk < 16; kk++) {
            const unsigned long long* ap =
                (const unsigned long long*)&sm->gemm.As[cur][kk][ty * 8];
            unsigned long long a0 = ap[0], a1 = ap[1], a2 = ap[2], a3 = ap[3];
            float4 bv = *(const float4*)&sm->gemm.Bs[cur][kk][tx * 4];
            unsigned long long b0 = pk2(bv.x), b1 = pk2(bv.y),
                               b2 = pk2(bv.z), b3 = pk2(bv.w);
            fma2(acc[0][0], a0, b0); fma2(acc[0][1], a0, b1);
            fma2(acc[0][2], a0, b2); fma2(acc[0][3], a0, b3);
            fma2(acc[1][0], a1, b0); fma2(acc[1][1], a1, b1);
            fma2(acc[1][2], a1, b2); fma2(acc[1][3], a1, b3);
            fma2(acc[2][0], a2, b0); fma2(acc[2][1], a2, b1);
            fma2(acc[2][2], a2, b2); fma2(acc[2][3], a2, b3);
            fma2(acc[3][0], a3, b0); fma2(acc[3][1], a3, b1);
            fma2(acc[3][2], a3, b2); fma2(acc[3][3], a3, b3);
        }
        if (c < 3) {
            const int nxt = cur ^ 1;
            sm->gemm.As[nxt][aj + 0][ai] = na.x;
            sm->gemm.As[nxt][aj + 1][ai] = na.y;
            sm->gemm.As[nxt][aj + 2][ai] = na.z;
            sm->gemm.As[nxt][aj + 3][ai] = na.w;
            *(float4*)&sm->gemm.Bs[nxt][bk][bc] = nb;
        }
        __syncthreads();
    }

#pragma unroll
    for (int u = 0; u < 4; u++) {
        int r0 = row0 + ty * 8 + u * 2;
        if (r0 < m && (col0 + tx * 4) < m) {
            float2 p0 = upk(acc[u][0]), p1 = upk(acc[u][1]);
            float2 p2 = upk(acc[u][2]), p3 = upk(acc[u][3]);
            float4* c0 = (float4*)&d_J[(size_t)(k2 + r0) * LDA + k2 + col0 + tx * 4];
            float4 v0 = *c0;
            v0.x -= p0.x; v0.y -= p1.x; v0.z -= p2.x; v0.w -= p3.x;
            *c0 = v0;
            float4* c1 = (float4*)&d_J[(size_t)(k2 + r0 + 1) * LDA + k2 + col0 + tx * 4];
            float4 v1 = *c1;
            v1.x -= p0.y; v1.y -= p1.y; v1.z -= p2.y; v1.w -= p3.y;
            *c1 = v1;
        }
    }
}

/* ---------- forward y-update: y[r0..r1) -= L21(rows) . y_k (64-wide) ---------- */
__device__ __forceinline__ void y_update_range(int k, int r0, int r1)
{
    const int warp = threadIdx.x >> 5, lane = threadIdx.x & 31;
    const float ylo = d_y[k + lane];
    const float yhi = d_y[k + 32 + lane];
    for (int r = r0 + warp; r < r1; r += NWARPS) {
        const float* row = &d_J[(size_t)r * LDA + k];
        float s = row[lane] * ylo + row[lane + 32] * yhi;
#pragma unroll
        for (int o = 16; o; o >>= 1) s += __shfl_down_sync(0xffffffffu, s, o);
        if (lane == 0) d_y[r] -= s;
    }
}

/* ---------- 128-wide backward diag solve, 1 sync per column ---------- */
__device__ void subst_diag_bwd128(int k, SM* sm)
{
    int t = threadIdx.x;
    __syncthreads();
    for (int idx = t; idx < 128 * 128; idx += NTHREADS)
        sm->sub.m[idx >> 7][idx & 127] = d_J[(size_t)(k + (idx >> 7)) * LDA + k + (idx & 127)];
    float yt = 0.f, invt = 0.f;
    if (t < 128) yt = d_y[k + t];
    __syncthreads();
    if (t < 128) invt = 1.f / sm->sub.m[t][t];
    for (int j = 127; j >= 0; j--) {
        if (t == j) { yt *= invt; sm->sub.val[j] = yt; }
        __syncthreads();
        if (t < j) yt -= sm->sub.m[t][j] * sm->sub.val[j];
    }
    if (t < 128) d_y[k + t] = yt;
    __syncthreads();
}

/* ---------- one 128-wide dot for bwd substitution row update ---------- */
__device__ __forceinline__ void row_update(int r, int k, const float* yc, int lane)
{
    const float* row = &d_J[(size_t)r * LDA + k];
    float s = row[lane] * yc[lane] + row[lane + 32] * yc[lane + 32]
            + row[lane + 64] * yc[lane + 64] + row[lane + 96] * yc[lane + 96];
#pragma unroll
    for (int o = 16; o; o >>= 1) s += __shfl_down_sync(0xffffffffu, s, o);
    if (lane == 0) d_y[r] -= s;
}

/* ---------- RHS value for row i ---------- */
__device__ __forceinline__ float rhs_val(const Params& P, int i)
{
    if (i < NB) {
        float vm = d_x[NB + i];
        return (P.bt[i] == 3) ? d_x[i]
                              : (P.p_spec[i] - (d_Pacc[i] + vm * vm * P.gs[i]));
    } else if (i < DIM) {
        int ib = i - NB;
        float vm = d_x[i];
        return (P.bt[ib] >= 2) ? (vm - P.vmset[ib])
                               : (P.q_spec[ib] - (d_Qacc[ib] - vm * vm * P.bs[ib]));
    }
    return 0.f;
}

#define GSYNC() do { gen++; gsync(gen); } while (0)

/* =======================================================================
 *  The one persistent kernel
 * ======================================================================= */
__global__ void __launch_bounds__(NTHREADS, 1) solver_kernel(Params P)
{
    extern __shared__ char s_raw[];
    SM* sm = (SM*)s_raw;
    const int tid = threadIdx.x;
    const int gsize = gridDim.x * NTHREADS;
    const int gtid = blockIdx.x * NTHREADS + tid;
    const int warp = tid >> 5, lane = tid & 31;
    unsigned gen = 0;

    /* init: state, masks, flags, zero J+accs for step 0 */
    for (int i = gtid; i < DIMP; i += gsize) {
        d_x[i] = (i < DIM) ? P.x_in[i] : 0.0f;
        if (i < NB) {
            int b = P.bt[i];
            d_kp[i] = (b == 3) ? 0.f : 1.f;
            d_kq[i] = (b >= 2) ? 0.f : 1.f;
        }
        if (i < 64) { d_rowflag[i] = 0u; d_colflag[i] = 0u; }
    }
    {
        size_t tot = (size_t)DIMP * LDA / 4;
        float4 z = make_float4(0.f, 0.f, 0.f, 0.f);
        for (size_t i = gtid; i < tot; i += gsize) ((float4*)d_J)[i] = z;
        for (int i = gtid; i < NB; i += gsize) { d_Pacc[i] = 0.f; d_Qacc[i] = 0.f; }
    }
    GSYNC();

    for (int t5 = 0; t5 < 5; t5++) {
        /* ---- assembly phase: edges + diag-J adds + padding diag ---- */
        for (int e = gtid; e < NE; e += gsize) {
            int s = P.ei[e], d = P.ei[NE + e];
            float vm_s = d_x[NB + s], vm_d = d_x[NB + d];
            float r = P.br_r[e], xx = P.br_x[e];
            float den = r * r + xx * xx;
            float g = r / den, b = -xx / den;
            float tp = P.tap[e];
            float th = d_x[s] - d_x[d];
            float sf, cf;
            sincosf(th - P.shift[e], &sf, &cf);
            float ct = cf, st = -sf;
            float vi_t = vm_s / tp;
            float vij = vm_s * vm_d / tp;

            float gfr = P.g_fr[e], bfr = P.b_fr[e], gto = P.g_to[e], bto = P.b_to[e];
            float Pf = vi_t * vi_t * (g + gfr) + vij * (-g * cf - b * sf);
            float Qf = -vi_t * vi_t * (b + bfr) + vij * (-g * sf + b * cf);
            float Pt = vm_d * vm_d * (g + gto) + vij * (-g * ct - b * st);
            float Qt = -vm_d * vm_d * (b + bto) + vij * (-g * st + b * ct);
            atomicAdd(&d_Pacc[s], Pf); atomicAdd(&d_Pacc[d], Pt);
            atomicAdd(&d_Qacc[s], Qf); atomicAdd(&d_Qacc[d], Qt);

            float Af = g * cf + b * sf, Bf = g * sf - b * cf;
            float At = g * ct + b * st, Bt = g * st - b * ct;
            size_t Rs  = (size_t)s * LDA, Rd = (size_t)d * LDA;
            size_t Rqs = (size_t)(NB + s) * LDA, Rqd = (size_t)(NB + d) * LDA;

            if (d_kp[s] != 0.f) {
                atomicAdd(&d_J[Rs + s],      -vij * Bf);
                atomicAdd(&d_J[Rs + d],       vij * Bf);
                atomicAdd(&d_J[Rs + NB + s], -(2.f * vm_s / (tp * tp) * (g + gfr) - vm_d / tp * Af));
                atomicAdd(&d_J[Rs + NB + d],  (vm_s / tp) * Af);
            }
            if (d_kp[d] != 0.f) {
                atomicAdd(&d_J[Rd + d],      -vij * Bt);
                atomicAdd(&d_J[Rd + s],       vij * Bt);
                atomicAdd(&d_J[Rd + NB + d], -(2.f * vm_d * (g + gto) - vm_s / tp * At));
                atomicAdd(&d_J[Rd + NB + s],  (vm_d / tp) * At);
            }
            if (d_kq[s] != 0.f) {
                atomicAdd(&d_J[Rqs + s],      vij * Af);
                atomicAdd(&d_J[Rqs + d],     -vij * Af);
                atomicAdd(&d_J[Rqs + NB + s], (2.f * vm_s / (tp * tp) * (b + bfr) + vm_d / tp * Bf));
                atomicAdd(&d_J[Rqs + NB + d], (vm_s / tp) * Bf);
            }
            if (d_kq[d] != 0.f) {
                atomicAdd(&d_J[Rqd + d],      vij * At);
                atomicAdd(&d_J[Rqd + s],     -vij * At);
                atomicAdd(&d_J[Rqd + NB + d], (2.f * vm_d * (b + bto) + vm_s / tp * Bt));
                atomicAdd(&d_J[Rqd + NB + s], (vm_s / tp) * Bt);
            }
        }
        for (int i = gtid; i < NB; i += gsize) {
            int b = P.bt[i];
            float vm = d_x[NB + i];
            atomicAdd(&d_J[(size_t)i * LDA + i], ((b == 3) ? 1.f : 0.f) + EPSJ);
            atomicAdd(&d_J[(size_t)i * LDA + NB + i], d_kp[i] * (-2.f * vm * P.gs[i]));
            atomicAdd(&d_J[(size_t)(NB + i) * LDA + (NB + i)],
                      d_kq[i] * (2.f * vm * P.bs[i]) + ((b >= 2) ? 1.f : 0.f) + EPSJ);
        }
        for (int i = DIM + gtid; i < DIMP; i += gsize)
            d_J[(size_t)i * LDA + i] = 1.0f;
        GSYNC();

        /* ---- RHS + lu_diag(0) in one phase ---- */
        if (blockIdx.x == 0) {
            if (tid < 64) d_y[tid] = rhs_val(P, tid);
            __syncthreads();
            lu_diag(0, sm);
        } else {
            for (int i = 64 + (blockIdx.x - 1) * NTHREADS + tid; i < DIMP;
                 i += (gridDim.x - 1) * NTHREADS)
                d_y[i] = rhs_val(P, i);
        }
        GSYNC();

        /* ---- blocked LU (fwd subst folded), 1 phase/panel, corner lookahead ---- */
        for (int k = 0; k + 64 < DIMP; k += 64) {
            const int m = DIMP - k - 64;
            const int ntr = m / 64;
            const int g = (m + 127) / 128;
            const unsigned epoch = (unsigned)(t5 * 64 + (k >> 6) + 1);
            const int bid = blockIdx.x;

            if (bid == 0) {
                if (tid == 0) {
                    wait_flag(&d_rowflag[0], epoch);
                    wait_flag(&d_colflag[0], epoch);
                    __threadfence();
                }
                __syncthreads();
                y_update_range(k, k + 64, k + 128);
                gemm_block64<64>(k, 0, 0, sm);        /* corner of next diag */
                lu_diag(k + 64, sm);
                if (k == DIMP - 128) subst_diag_bwd128(k, sm); /* first bwd solve */
            } else {
                /* dedicated TRSM jobs: each is a block's FIRST work item */
                for (int j = bid - 1; j < 2 * ntr; j += gridDim.x - 1) {
                    if (j < ntr) {
                        trsm_row(k, k + 64 + j * 64, sm);
                        __syncthreads();
                        if (tid == 0) { __threadfence(); d_rowflag[j] = epoch; }
                    } else {
                        int i2 = j - ntr;
                        trsm_col(k, k + 64 + i2 * 64, sm);
                        __syncthreads();
                        if (tid == 0) { __threadfence(); d_colflag[i2] = epoch; }
                    }
                }
                /* pool: quadrants of tile(0,0), y-updates, GEMM tiles */
                const int nq = (m >= 128) ? 2 : 0;
                const int nyj = ntr - 1;
                const int njobs = nq + nyj + g * g - 1;
                for (int job = bid - 1; job < njobs; job += gridDim.x - 1) {
                    if (job < nq) {
                        if (job == 0) {       /* rows 64-127 x cols 0-127 */
                            if (tid == 0) {
                                wait_flag(&d_rowflag[1], epoch);
                                wait_flag(&d_colflag[0], epoch);
                                wait_flag(&d_colflag[1], epoch);
                                __threadfence();
                            }
                            __syncthreads();
                            gemm_block64<128>(k, 64, 0, sm);
                        } else {              /* rows 0-63 x cols 64-127 */
                            if (tid == 0) {
                                wait_flag(&d_rowflag[0], epoch);
                                wait_flag(&d_colflag[1], epoch);
                                __threadfence();
                            }
                            __syncthreads();
                            gemm_block64<64>(k, 0, 64, sm);
                        }
                    } else if (job < nq + nyj) {
                        int rt = job - nq + 1;
                        if (tid == 0) { wait_flag(&d_rowflag[rt], epoch); __threadfence(); }
                        __syncthreads();
                        int r0 = k + 64 + rt * 64;
                        y_update_range(k, r0, r0 + 64);
                    } else {
                        int t2 = job - nq - nyj + 1;
                        int r = t2 / g, c = t2 % g;
                        if (tid == 0) {
                            wait_flag(&d_rowflag[2 * r], epoch);
                            if (2 * r + 1 < ntr) wait_flag(&d_rowflag[2 * r + 1], epoch);
                            wait_flag(&d_colflag[2 * c], epoch);
                            if (2 * c + 1 < ntr) wait_flag(&d_colflag[2 * c + 1], epoch);
                            __threadfence();
                        }
                        __syncthreads();
                        gemm_tile(k, m, r * 128, c * 128, sm);
                    }
                }
            }
            GSYNC();
        }
        /* d_y holds L^{-1} F; diag(DIMP-128) panel already solved */

        /* ---- backward substitution, 128-wide panels, block-0 lookahead ---- */
        for (int k = DIMP - PW; k > 0; k -= PW) {
            __syncthreads();
            if (tid < PW) sm->sub.yc[tid] = d_y[k + tid];
            __syncthreads();
            if (blockIdx.x == 0) {
                for (int r = k - PW + warp; r < k; r += NWARPS)
                    row_update(r, k, sm->sub.yc, lane);
                __syncthreads();
                subst_diag_bwd128(k - PW, sm);
            } else {
                int gw = (blockIdx.x - 1) * NWARPS + warp;
                int tot = (gridDim.x - 1) * NWARPS;
                for (int r = gw; r < k - PW; r += tot)
                    row_update(r, k, sm->sub.yc, lane);
            }
            GSYNC();
        }

        /* ---- Newton update + zero J/accs for next step ---- */
        for (int i = gtid; i < DIM; i += gsize) {
            float v = d_x[i] - d_y[i];
            if (i >= NB) v = fminf(fmaxf(v, 0.5f), 1.5f);
            d_x[i] = v;
        }
        if (t5 < 4) {
            size_t tot = (size_t)DIMP * LDA / 4;
            float4 z = make_float4(0.f, 0.f, 0.f, 0.f);
            for (size_t i = gtid; i < tot; i += gsize) ((float4*)d_J)[i] = z;
            for (int i = gtid; i < NB; i += gsize) { d_Pacc[i] = 0.f; d_Qacc[i] = 0.f; }
        }
        GSYNC();
    }

    for (int i = gtid; i < DIM; i += gsize)
        P.out[i] = d_x[i];
}

extern "C" void kernel_launch(void* const* d_in, const int* in_sizes, int n_in,
                              void* d_out, int out_size)
{
    Params P;
    P.x_in   = (const float*)d_in[0];
    P.ei     = (const int*)  d_in[1];
    P.br_r   = (const float*)d_in[2];
    P.br_x   = (const float*)d_in[3];
    P.g_fr   = (const float*)d_in[4];
    P.b_fr   = (const float*)d_in[5];
    P.g_to   = (const float*)d_in[6];
    P.b_to   = (const float*)d_in[7];
    P.tap    = (const float*)d_in[8];
    P.shift  = (const float*)d_in[9];
    P.p_spec = (const float*)d_in[10];
    P.q_spec = (const float*)d_in[11];
    P.gs     = (const float*)d_in[12];
    P.bs     = (const float*)d_in[13];
    P.bt     = (const int*)  d_in[14];
    P.vmset  = (const float*)d_in[15];
    P.out    = (float*)d_out;

    cudaFuncSetAttribute(solver_kernel,
                         cudaFuncAttributeMaxDynamicSharedMemorySize,
                         (int)SMEM_BYTES);

    int dev = 0, nsm = 0, per_sm = 0;
    cudaGetDevice(&dev);
    cudaDeviceGetAttribute(&nsm, cudaDevAttrMultiProcessorCount, dev);
    cudaOccupancyMaxActiveBlocksPerMultiprocessor(&per_sm, solver_kernel,
                                                  NTHREADS, SMEM_BYTES);
    if (per_sm < 1) per_sm = 1;
    int grid = nsm * per_sm;
    if (grid < 4) grid = 4;
    if (grid > 1024) grid = 1024;

    solver_kernel<<<grid, NTHREADS, SMEM_BYTES>>>(P);
}